// round 6
// baseline (speedup 1.0000x reference)
#include <cuda_runtime.h>
#include <cuda_bf16.h>
#include <math.h>
#include <stdint.h>

#define BATCH 32
#define DIM 256
#define NTOK 4096
#define NSLOT 8
#define MTOT (BATCH*NTOK)

// ---------------- scratch (device globals; no runtime allocation) ----------------
__device__ float g_bufA[BATCH*NTOK*DIM];   // fm2 out / V
__device__ float g_bufC[BATCH*NTOK*DIM];   // K
__device__ __nv_bfloat16 g_ahi[MTOT*DIM];  // GEMM input planes (hi)
__device__ __nv_bfloat16 g_alo[MTOT*DIM];  // (lo)
__device__ __nv_bfloat16 g_bhi[MTOT*DIM];  // fm1 out planes
__device__ __nv_bfloat16 g_blo[MTOT*DIM];
__device__ float g_pos[NTOK*DIM];          // [t][d]
__device__ float g_posT[DIM*NTOK];         // [d][t]
__device__ float g_part[BATCH*256*2];
__device__ float g_stats[BATCH*2];
__device__ float g_attn[BATCH*NSLOT*NTOK];
__device__ float g_rinv[BATCH*NSLOT];
__device__ float g_q[BATCH*NSLOT*DIM];
__device__ float g_updp[BATCH*8*NSLOT*DIM];
__device__ float g_upd[BATCH*NSLOT*DIM];
__device__ float g_slots[BATCH*NSLOT*DIM];
__device__ __nv_bfloat16 g_whi[4*DIM*DIM]; // weights [N][K] bf16 hi
__device__ __nv_bfloat16 g_wlo[4*DIM*DIM]; // weights [N][K] bf16 lo

__device__ __forceinline__ float wred(float v){
    #pragma unroll
    for (int o = 16; o; o >>= 1) v += __shfl_xor_sync(0xffffffffu, v, o);
    return v;
}
__device__ __forceinline__ uint32_t smem_u32(const void* p){
    uint32_t a;
    asm("{ .reg .u64 t; cvta.to.shared.u64 t, %1; cvt.u32.u64 %0, t; }" : "=r"(a) : "l"(p));
    return a;
}
__device__ __forceinline__ void ldsm4(uint32_t* r, uint32_t addr){
    asm volatile("ldmatrix.sync.aligned.m8n8.x4.shared.b16 {%0,%1,%2,%3}, [%4];"
        : "=r"(r[0]), "=r"(r[1]), "=r"(r[2]), "=r"(r[3]) : "r"(addr));
}
__device__ __forceinline__ void mma16816(float* c, const uint32_t* a, const uint32_t* b){
    asm volatile("mma.sync.aligned.m16n8k16.row.col.f32.bf16.bf16.f32 "
        "{%0,%1,%2,%3}, {%4,%5,%6,%7}, {%8,%9}, {%0,%1,%2,%3};"
        : "+f"(c[0]), "+f"(c[1]), "+f"(c[2]), "+f"(c[3])
        : "r"(a[0]), "r"(a[1]), "r"(a[2]), "r"(a[3]), "r"(b[0]), "r"(b[1]));
}
__device__ __forceinline__ uint32_t sw128(uint32_t boff){
    return boff ^ ((boff >> 3) & 0x70);
}
__device__ __forceinline__ void cpa16(uint32_t s, const void* g){
    asm volatile("cp.async.cg.shared.global [%0], [%1], 16;" :: "r"(s), "l"(g));
}
__device__ __forceinline__ void cpa_commit(){
    asm volatile("cp.async.commit_group;");
}

// ---------------- weight prep: transpose [K,N]->[N,K], split hi/lo ----------------
__global__ void prep_w_k(const float* __restrict__ w, __nv_bfloat16* __restrict__ whi,
                         __nv_bfloat16* __restrict__ wlo){
    int idx = blockIdx.x*256 + threadIdx.x;   // n*256 + k
    int n = idx >> 8, k = idx & 255;
    float a = w[k*256 + n];
    __nv_bfloat16 h = __float2bfloat16(a);
    float r = a - __bfloat162float(h);
    whi[idx] = h;
    wlo[idx] = __float2bfloat16(r);
}

// ---------------- HMMA GEMM: C[M,256] = act(Ahl @ Whl + bias) ----------------
// A pre-split bf16 hi/lo planes [M][256]; weights [N][256] hi/lo.
// CTA 128x128, 8 warps 4x2; K-chunk 32, double-buffered cp.async, 1 sync/chunk.
// mode: 0 = fp32 out, 1 = fp32 relu out, 2 = relu + bf16 hi/lo out,
//       3 = dual-weight fp32 out (grid.y=4; y<2 -> set1, y>=2 -> set2)
__global__ void __launch_bounds__(256) mma_gemm_k(
        const __nv_bfloat16* __restrict__ Ahi, const __nv_bfloat16* __restrict__ Alo,
        const __nv_bfloat16* __restrict__ Bhi, const __nv_bfloat16* __restrict__ Blo,
        const float* __restrict__ bias,
        float* __restrict__ C,
        __nv_bfloat16* __restrict__ Chi, __nv_bfloat16* __restrict__ Clo,
        int mode,
        const __nv_bfloat16* __restrict__ B2hi, const __nv_bfloat16* __restrict__ B2lo,
        const float* __restrict__ bias2, float* __restrict__ C2){
    extern __shared__ char dsm[];
    __shared__ float s_bias[256];
    int tid = threadIdx.x;
    uint32_t raw = smem_u32(dsm);
    uint32_t sb = (raw + 1023) & ~1023u;
    uint32_t aAH = sb, aAL = sb + 16384, aBH = sb + 32768, aBL = sb + 49152;

    const __nv_bfloat16* Wh = Bhi;
    const __nv_bfloat16* Wl = Blo;
    const float* bi = bias;
    float* Co = C;
    size_t bn;
    if (mode == 3){
        if (blockIdx.y >= 2){ Wh = B2hi; Wl = B2lo; bi = bias2; Co = C2; }
        bn = (size_t)(blockIdx.y & 1) * 128;
    } else {
        bn = (size_t)blockIdx.y * 128;
    }
    s_bias[tid] = bi[tid];

    size_t bm = (size_t)blockIdx.x * 128;
    int lane = tid & 31, wid = tid >> 5;
    int wm = wid & 3, wn = wid >> 2;

    float acc[2][8][4] = {};

    auto prefetch = [&](int c, int buf){
        int k0 = c * 32;
        #pragma unroll
        for (int p = 0; p < 2; p++){
            int id = tid + p*256;        // 0..511
            int row = id >> 2, qc = id & 3;
            uint32_t soff = sw128((uint32_t)(row*128 + buf*64 + qc*16));
            size_t ga = (bm + row)*256 + k0 + qc*8;
            size_t gb = (bn + row)*256 + k0 + qc*8;
            cpa16(aAH + soff, Ahi + ga);
            cpa16(aAL + soff, Alo + ga);
            cpa16(aBH + soff, Wh + gb);
            cpa16(aBL + soff, Wl + gb);
        }
    };

    prefetch(0, 0);
    cpa_commit();

    #pragma unroll 1
    for (int c = 0; c < 8; c++){
        int buf = c & 1;
        asm volatile("cp.async.wait_group 0;");
        __syncthreads();
        if (c < 7){
            prefetch(c+1, buf ^ 1);
            cpa_commit();
        }

        #pragma unroll
        for (int s2 = 0; s2 < 2; s2++){
            uint32_t cb = (uint32_t)(buf*64 + s2*32);
            uint32_t Ah[2][4], Al[2][4], Bh[8][2], Bl[8][2];
            #pragma unroll
            for (int i = 0; i < 2; i++){
                uint32_t row = wm*32 + i*16 + (lane & 15);
                uint32_t sw = sw128(row*128 + cb + (lane >> 4)*16);
                ldsm4(Ah[i], aAH + sw);
                ldsm4(Al[i], aAL + sw);
            }
            #pragma unroll
            for (int j2 = 0; j2 < 4; j2++){
                uint32_t row = wn*64 + j2*16 + (lane >> 4)*8 + (lane & 7);
                uint32_t sw = sw128(row*128 + cb + ((lane >> 3) & 1)*16);
                uint32_t r[4];
                ldsm4(r, aBH + sw);
                Bh[2*j2][0] = r[0]; Bh[2*j2][1] = r[1];
                Bh[2*j2+1][0] = r[2]; Bh[2*j2+1][1] = r[3];
                ldsm4(r, aBL + sw);
                Bl[2*j2][0] = r[0]; Bl[2*j2][1] = r[1];
                Bl[2*j2+1][0] = r[2]; Bl[2*j2+1][1] = r[3];
            }
            #pragma unroll
            for (int i = 0; i < 2; i++)
                #pragma unroll
                for (int j = 0; j < 8; j++){
                    mma16816(acc[i][j], Ah[i], Bh[j]);
                    mma16816(acc[i][j], Ah[i], Bl[j]);
                    mma16816(acc[i][j], Al[i], Bh[j]);
                }
        }
    }

    int row0 = (int)bm + wm*32 + (lane >> 2);
    int col0 = (int)bn + wn*64 + 2*(lane & 3);
    #pragma unroll
    for (int i = 0; i < 2; i++){
        #pragma unroll
        for (int j = 0; j < 8; j++){
            int col = col0 + j*8;
            float b0 = s_bias[col], b1 = s_bias[col+1];
            float v00 = acc[i][j][0] + b0, v01 = acc[i][j][1] + b1;
            float v10 = acc[i][j][2] + b0, v11 = acc[i][j][3] + b1;
            if (mode == 1 || mode == 2){
                v00 = fmaxf(v00, 0.f); v01 = fmaxf(v01, 0.f);
                v10 = fmaxf(v10, 0.f); v11 = fmaxf(v11, 0.f);
            }
            size_t r0 = (size_t)(row0 + i*16)*256 + col;
            size_t r1 = r0 + 8*256;
            if (mode == 2){
                __nv_bfloat16 h00 = __float2bfloat16(v00), h01 = __float2bfloat16(v01);
                __nv_bfloat16 h10 = __float2bfloat16(v10), h11 = __float2bfloat16(v11);
                *(__nv_bfloat162*)&Chi[r0] = __halves2bfloat162(h00, h01);
                *(__nv_bfloat162*)&Chi[r1] = __halves2bfloat162(h10, h11);
                *(__nv_bfloat162*)&Clo[r0] = __halves2bfloat162(
                    __float2bfloat16(v00 - __bfloat162float(h00)),
                    __float2bfloat16(v01 - __bfloat162float(h01)));
                *(__nv_bfloat162*)&Clo[r1] = __halves2bfloat162(
                    __float2bfloat16(v10 - __bfloat162float(h10)),
                    __float2bfloat16(v11 - __bfloat162float(h11)));
            } else {
                float2 o0 = {v00, v01}, o1 = {v10, v11};
                *(float2*)&Co[r0] = o0;
                *(float2*)&Co[r1] = o1;
            }
        }
    }
}

// ---------------- positional embedding (both layouts) ----------------
__global__ void pos_k(const float* __restrict__ pw, const float* __restrict__ pb){
    int idx = blockIdx.x*256 + threadIdx.x;
    int t = idx >> 8, d = idx & 255;
    float gx = (float)(t >> 6) * (1.0f/63.0f);
    float gy = (float)(t & 63) * (1.0f/63.0f);
    float v = gx*pw[d] + gy*pw[256+d] + (1.f-gx)*pw[512+d] + (1.f-gy)*pw[768+d] + pb[d];
    g_pos[t*DIM + d] = v;
    g_posT[d*NTOK + t] = v;
}

// ---------------- whole-image LN stats (deterministic 2-stage) ----------------
__global__ void __launch_bounds__(256) stats_partial_k(const float* __restrict__ x){
    int b = blockIdx.y, p = blockIdx.x, tid = threadIdx.x;
    const float* xb = x + (size_t)b*(DIM*NTOK) + (size_t)p*NTOK;
    const float* pt = g_posT + (size_t)p*NTOK;
    float s = 0.f, sq = 0.f;
    #pragma unroll
    for (int j = 0; j < 16; j++){
        float v = xb[tid + j*256] + pt[tid + j*256];
        s += v; sq += v*v;
    }
    __shared__ float ss[256], sqs[256];
    ss[tid] = s; sqs[tid] = sq; __syncthreads();
    for (int st = 128; st; st >>= 1){
        if (tid < st){ ss[tid] += ss[tid+st]; sqs[tid] += sqs[tid+st]; }
        __syncthreads();
    }
    if (!tid){ g_part[(b*256+p)*2] = ss[0]; g_part[(b*256+p)*2+1] = sqs[0]; }
}

__global__ void stats_final_k(){
    int b = blockIdx.x, tid = threadIdx.x;
    __shared__ float ss[256], sqs[256];
    ss[tid]  = g_part[(b*256+tid)*2];
    sqs[tid] = g_part[(b*256+tid)*2+1];
    __syncthreads();
    for (int st = 128; st; st >>= 1){
        if (tid < st){ ss[tid] += ss[tid+st]; sqs[tid] += sqs[tid+st]; }
        __syncthreads();
    }
    if (!tid){
        const float invN = 1.0f/1048576.0f;
        float m = ss[0]*invN;
        float var = sqs[0]*invN - m*m;
        g_stats[b*2] = m;
        g_stats[b*2+1] = rsqrtf(var + 1e-5f);
    }
}

// ---------------- normalize + transpose -> hi/lo token planes ----------------
__global__ void __launch_bounds__(256) norm_tok_k(const float* __restrict__ x,
                                                  const float* __restrict__ eg,
                                                  const float* __restrict__ eb){
    __shared__ float sh[32][33];
    int b = blockIdx.z;
    int d0 = blockIdx.y*32, t0 = blockIdx.x*32;
    int tx = threadIdx.x, ty = threadIdx.y;
    float mean = g_stats[b*2], rstd = g_stats[b*2+1];
    const float* xb = x + (size_t)b*(DIM*NTOK);
    #pragma unroll
    for (int r = 0; r < 4; r++)
        sh[ty+8*r][tx] = xb[(size_t)(d0+ty+8*r)*NTOK + t0 + tx];
    __syncthreads();
    size_t ob = (size_t)b*(NTOK*DIM);
    #pragma unroll
    for (int r = 0; r < 4; r++){
        int trow = t0 + ty + 8*r;
        int dcol = d0 + tx;
        int pi = trow*DIM + dcol;
        float v = sh[tx][ty+8*r] + g_pos[pi];
        float o = (v - mean)*rstd*eg[pi] + eb[pi];
        __nv_bfloat16 h = __float2bfloat16(o);
        g_ahi[ob + pi] = h;
        g_alo[ob + pi] = __float2bfloat16(o - __bfloat162float(h));
    }
}

// ---------------- per-token LayerNorm -> hi/lo planes ----------------
__global__ void __launch_bounds__(256) token_ln_k(const float* __restrict__ A,
                                                  const float* __restrict__ g,
                                                  const float* __restrict__ be){
    int warp = threadIdx.x >> 5, lane = threadIdx.x & 31;
    size_t row = (size_t)blockIdx.x*8 + warp;
    const float4* r4 = (const float4*)(A + row*DIM);
    float4 v0 = r4[lane], v1 = r4[lane+32];
    float s  = v0.x+v0.y+v0.z+v0.w + v1.x+v1.y+v1.z+v1.w;
    float sq = v0.x*v0.x+v0.y*v0.y+v0.z*v0.z+v0.w*v0.w
             + v1.x*v1.x+v1.y*v1.y+v1.z*v1.z+v1.w*v1.w;
    s = wred(s); sq = wred(sq);
    float m = s*(1.0f/256.0f);
    float var = sq*(1.0f/256.0f) - m*m;
    float rs = rsqrtf(var + 1e-5f);
    const float4* g4 = (const float4*)g;
    const float4* b4 = (const float4*)be;
    float4 ga = g4[lane], gb = g4[lane+32], ba = b4[lane], bb = b4[lane+32];
    float o[8];
    o[0] = (v0.x-m)*rs*ga.x + ba.x; o[1] = (v0.y-m)*rs*ga.y + ba.y;
    o[2] = (v0.z-m)*rs*ga.z + ba.z; o[3] = (v0.w-m)*rs*ga.w + ba.w;
    o[4] = (v1.x-m)*rs*gb.x + bb.x; o[5] = (v1.y-m)*rs*gb.y + bb.y;
    o[6] = (v1.z-m)*rs*gb.z + bb.z; o[7] = (v1.w-m)*rs*gb.w + bb.w;
    __nv_bfloat162* H2 = (__nv_bfloat162*)(g_ahi + row*DIM);
    __nv_bfloat162* L2 = (__nv_bfloat162*)(g_alo + row*DIM);
    #pragma unroll
    for (int h2 = 0; h2 < 2; h2++){
        #pragma unroll
        for (int q2 = 0; q2 < 2; q2++){
            float a0 = o[h2*4 + q2*2], a1 = o[h2*4 + q2*2 + 1];
            __nv_bfloat16 hh0 = __float2bfloat16(a0), hh1 = __float2bfloat16(a1);
            int pidx = h2*64 + lane*2 + q2;
            H2[pidx] = __halves2bfloat162(hh0, hh1);
            L2[pidx] = __halves2bfloat162(
                __float2bfloat16(a0 - __bfloat162float(hh0)),
                __float2bfloat16(a1 - __bfloat162float(hh1)));
        }
    }
}

// ---------------- slots init ----------------
__global__ void slots_init_k(const float* __restrict__ eps, const float* __restrict__ loc,
                             const float* __restrict__ lsc){
    int idx = blockIdx.x*256 + threadIdx.x;
    int d = idx & 255;
    g_slots[idx] = loc[d] + expf(lsc[d]) * eps[idx];
}

// ---------------- slot LN + Q projection ----------------
__global__ void __launch_bounds__(256) slotln_q_k(const float* __restrict__ sg,
                                                  const float* __restrict__ sb,
                                                  const float* __restrict__ qw,
                                                  const float* __restrict__ qb){
    __shared__ float sn[8][256];
    int b = blockIdx.x, tid = threadIdx.x, warp = tid >> 5, lane = tid & 31;
    const float* sl = g_slots + (b*8 + warp)*256;
    float v[8]; float s = 0.f, sq = 0.f;
    #pragma unroll
    for (int i = 0; i < 8; i++){ v[i] = sl[lane + 32*i]; s += v[i]; sq += v[i]*v[i]; }
    s = wred(s); sq = wred(sq);
    float m = s*(1.f/256.f), var = sq*(1.f/256.f) - m*m, rs = rsqrtf(var + 1e-5f);
    #pragma unroll
    for (int i = 0; i < 8; i++){
        int d = lane + 32*i;
        sn[warp][d] = (v[i]-m)*rs*sg[d] + sb[d];
    }
    __syncthreads();
    int c = tid;
    float acc[8] = {};
    for (int k = 0; k < 256; k++){
        float w = qw[k*256 + c];
        #pragma unroll
        for (int s2 = 0; s2 < 8; s2++) acc[s2] += sn[s2][k]*w;
    }
    float bq = qb[c];
    #pragma unroll
    for (int s2 = 0; s2 < 8; s2++) g_q[(b*8+s2)*256 + c] = acc[s2] + bq;
}

// ---------------- dots + softmax over slots (warp per token) ----------------
__global__ void __launch_bounds__(256) attn_k(){
    __shared__ __align__(16) float qs[2048];
    int b = blockIdx.y, tid = threadIdx.x;
    #pragma unroll
    for (int i = 0; i < 8; i++) qs[tid + 256*i] = g_q[b*2048 + tid + 256*i];
    __syncthreads();
    int warp = tid >> 5, lane = tid & 31;
    const float4* K4 = (const float4*)(g_bufC + (size_t)b*NTOK*DIM);
    int t0 = blockIdx.x*64 + warp*8;
    for (int tt = 0; tt < 8; tt++){
        int t = t0 + tt;
        float4 k0 = K4[t*64 + lane];
        float4 k1 = K4[t*64 + 32 + lane];
        float acc[8];
        #pragma unroll
        for (int s = 0; s < 8; s++){
            const float4* q4 = (const float4*)&qs[s*256];
            float4 q0 = q4[lane], q1 = q4[lane+32];
            acc[s] = k0.x*q0.x + k0.y*q0.y + k0.z*q0.z + k0.w*q0.w
                   + k1.x*q1.x + k1.y*q1.y + k1.z*q1.z + k1.w*q1.w;
        }
        #pragma unroll
        for (int s = 0; s < 8; s++) acc[s] = wred(acc[s]) * 0.0625f;
        float mx = acc[0];
        #pragma unroll
        for (int s = 1; s < 8; s++) mx = fmaxf(mx, acc[s]);
        float e[8], sum = 0.f;
        #pragma unroll
        for (int s = 0; s < 8; s++){ e[s] = expf(acc[s] - mx); sum += e[s]; }
        float inv = 1.f/sum;
        if (lane < 8)
            g_attn[((size_t)b*8 + lane)*NTOK + t] = e[lane]*inv + 1e-8f;
    }
}

// ---------------- deterministic rowsum over tokens ----------------
__global__ void __launch_bounds__(256) rowsum_k(){
    int bs = blockIdx.x, tid = threadIdx.x;
    const float* a = g_attn + (size_t)bs*NTOK;
    float s = 0.f;
    #pragma unroll
    for (int j = 0; j < 16; j++) s += a[tid + 256*j];
    __shared__ float sh[256];
    sh[tid] = s; __syncthreads();
    for (int st = 128; st; st >>= 1){
        if (tid < st) sh[tid] += sh[tid+st];
        __syncthreads();
    }
    if (!tid) g_rinv[bs] = 1.f/sh[0];
}

// ---------------- upd = attn @ V  (chunked, deterministic) ----------------
__global__ void __launch_bounds__(128) updpart_k(){
    int b = blockIdx.z, dt = blockIdx.y, c = blockIdx.x;
    int tid = threadIdx.x;
    int d = dt*128 + tid;
    __shared__ float as[8][128];
    float acc[8] = {};
    const float* V = g_bufA + (size_t)b*NTOK*DIM;
    for (int tb = c*512; tb < c*512 + 512; tb += 128){
        for (int i = tid; i < 1024; i += 128){
            int s = i >> 7, j = i & 127;
            as[s][j] = g_attn[((size_t)b*8 + s)*NTOK + tb + j];
        }
        __syncthreads();
        #pragma unroll 4
        for (int j = 0; j < 128; j++){
            float vv = V[(size_t)(tb+j)*256 + d];
            #pragma unroll
            for (int s = 0; s < 8; s++) acc[s] += as[s][j]*vv;
        }
        __syncthreads();
    }
    #pragma unroll
    for (int s = 0; s < 8; s++)
        g_updp[(((b*8)+c)*8 + s)*256 + d] = acc[s];
}

__global__ void updred_k(){
    int idx = blockIdx.x*256 + threadIdx.x;
    int b = idx >> 11, s = (idx >> 8) & 7, d = idx & 255;
    float sum = 0.f;
    #pragma unroll
    for (int c = 0; c < 8; c++) sum += g_updp[(((b*8)+c)*8 + s)*256 + d];
    g_upd[idx] = sum * g_rinv[b*8 + s];
}

// ---------------- GRU + pre-LN + residual MLP (one block per batch) ----------------
__global__ void __launch_bounds__(256) gru_k(const float* __restrict__ wih, const float* __restrict__ whh,
                                             const float* __restrict__ bih, const float* __restrict__ bhh,
                                             const float* __restrict__ pg,  const float* __restrict__ pb,
                                             const float* __restrict__ w1,  const float* __restrict__ b1,
                                             const float* __restrict__ w2,  const float* __restrict__ b2){
    __shared__ float su[8][256];
    __shared__ float sp[8][256];
    __shared__ float sf[8][256];
    int b = blockIdx.x, tid = threadIdx.x, warp = tid >> 5, lane = tid & 31;
    #pragma unroll
    for (int i = 0; i < 8; i++){
        su[i][tid] = g_upd[b*2048 + i*256 + tid];
        sp[i][tid] = g_slots[b*2048 + i*256 + tid];
    }
    __syncthreads();
    int c = tid;
    float gir[8] = {}, giz[8] = {}, gin[8] = {};
    float ghr[8] = {}, ghz[8] = {}, ghn[8] = {};
    for (int k = 0; k < 256; k++){
        float wi0 = wih[k*768 + c], wi1 = wih[k*768 + 256 + c], wi2 = wih[k*768 + 512 + c];
        float wh0 = whh[k*768 + c], wh1 = whh[k*768 + 256 + c], wh2 = whh[k*768 + 512 + c];
        #pragma unroll
        for (int s = 0; s < 8; s++){
            float us = su[s][k], ps = sp[s][k];
            gir[s] += us*wi0; giz[s] += us*wi1; gin[s] += us*wi2;
            ghr[s] += ps*wh0; ghz[s] += ps*wh1; ghn[s] += ps*wh2;
        }
    }
    float br = bih[c], bz = bih[256+c], bn_ = bih[512+c];
    float cr = bhh[c], cz = bhh[256+c], cn  = bhh[512+c];
    #pragma unroll
    for (int s = 0; s < 8; s++){
        float r = 1.f/(1.f + expf(-(gir[s]+br + ghr[s]+cr)));
        float z = 1.f/(1.f + expf(-(giz[s]+bz + ghz[s]+cz)));
        float n = tanhf(gin[s]+bn_ + r*(ghn[s]+cn));
        sf[s][c] = (1.f - z)*n + z*sp[s][c];
    }
    __syncthreads();
    {
        float v[8], s_ = 0.f, sq = 0.f;
        #pragma unroll
        for (int i = 0; i < 8; i++){ v[i] = sf[warp][lane+32*i]; s_ += v[i]; sq += v[i]*v[i]; }
        s_ = wred(s_); sq = wred(sq);
        float m = s_*(1.f/256.f), var = sq*(1.f/256.f) - m*m, rs = rsqrtf(var + 1e-5f);
        #pragma unroll
        for (int i = 0; i < 8; i++){
            int d = lane + 32*i;
            su[warp][d] = (v[i]-m)*rs*pg[d] + pb[d];
        }
    }
    __syncthreads();
    {
        float acc[8] = {};
        for (int k = 0; k < 256; k++){
            float w = w1[k*256 + c];
            #pragma unroll
            for (int s = 0; s < 8; s++) acc[s] += su[s][k]*w;
        }
        float bb = b1[c];
        #pragma unroll
        for (int s = 0; s < 8; s++) sp[s][c] = fmaxf(acc[s] + bb, 0.f);
    }
    __syncthreads();
    {
        float acc[8] = {};
        for (int k = 0; k < 256; k++){
            float w = w2[k*256 + c];
            #pragma unroll
            for (int s = 0; s < 8; s++) acc[s] += sp[s][k]*w;
        }
        float bb = b2[c];
        #pragma unroll
        for (int s = 0; s < 8; s++)
            g_slots[b*2048 + s*256 + c] = sf[s][c] + fmaxf(acc[s] + bb, 0.f);
    }
}

__global__ void copy_out_k(float* __restrict__ out){
    int idx = blockIdx.x*256 + threadIdx.x;
    out[idx] = g_slots[idx];
}

// ---------------- launch ----------------
extern "C" void kernel_launch(void* const* d_in, const int* in_sizes, int n_in,
                              void* d_out, int out_size){
    const float* x       = (const float*)d_in[0];
    const float* eps_n   = (const float*)d_in[1];
    const float* pos_w   = (const float*)d_in[2];
    const float* pos_b   = (const float*)d_in[3];
    const float* enc_g   = (const float*)d_in[4];
    const float* enc_b   = (const float*)d_in[5];
    const float* fm_w1   = (const float*)d_in[6];
    const float* fm_b1   = (const float*)d_in[7];
    const float* fm_w2   = (const float*)d_in[8];
    const float* fm_b2   = (const float*)d_in[9];
    const float* in_g    = (const float*)d_in[10];
    const float* in_b    = (const float*)d_in[11];
    const float* q_w     = (const float*)d_in[12];
    const float* q_b     = (const float*)d_in[13];
    const float* k_w     = (const float*)d_in[14];
    const float* k_b     = (const float*)d_in[15];
    const float* v_w     = (const float*)d_in[16];
    const float* v_b     = (const float*)d_in[17];
    const float* gru_wih = (const float*)d_in[18];
    const float* gru_whh = (const float*)d_in[19];
    const float* gru_bih = (const float*)d_in[20];
    const float* gru_bhh = (const float*)d_in[21];
    const float* pre_g   = (const float*)d_in[22];
    const float* pre_b   = (const float*)d_in[23];
    const float* st_w1   = (const float*)d_in[24];
    const float* st_b1   = (const float*)d_in[25];
    const float* st_w2   = (const float*)d_in[26];
    const float* st_b2   = (const float*)d_in[27];
    const float* slot_g  = (const float*)d_in[28];
    const float* slot_b  = (const float*)d_in[29];
    const float* sl_loc  = (const float*)d_in[30];
    const float* sl_lsc  = (const float*)d_in[31];

    float *bufA, *bufC;
    __nv_bfloat16 *whi, *wlo, *ahi, *alo, *bhi, *blo;
    cudaGetSymbolAddress((void**)&bufA, g_bufA);
    cudaGetSymbolAddress((void**)&bufC, g_bufC);
    cudaGetSymbolAddress((void**)&whi, g_whi);
    cudaGetSymbolAddress((void**)&wlo, g_wlo);
    cudaGetSymbolAddress((void**)&ahi, g_ahi);
    cudaGetSymbolAddress((void**)&alo, g_alo);
    cudaGetSymbolAddress((void**)&bhi, g_bhi);
    cudaGetSymbolAddress((void**)&blo, g_blo);

    const int GSMEM = 66560;
    cudaFuncSetAttribute(mma_gemm_k, cudaFuncAttributeMaxDynamicSharedMemorySize, GSMEM);

    prep_w_k<<<256, 256>>>(fm_w1, whi + 0*65536, wlo + 0*65536);
    prep_w_k<<<256, 256>>>(fm_w2, whi + 1*65536, wlo + 1*65536);
    prep_w_k<<<256, 256>>>(k_w,   whi + 2*65536, wlo + 2*65536);
    prep_w_k<<<256, 256>>>(v_w,   whi + 3*65536, wlo + 3*65536);

    pos_k<<<4096, 256>>>(pos_w, pos_b);
    stats_partial_k<<<dim3(256, BATCH), 256>>>(x);
    stats_final_k<<<BATCH, 256>>>();
    norm_tok_k<<<dim3(128, 8, BATCH), dim3(32, 8)>>>(x, enc_g, enc_b);

    // fm1: tokens(hi/lo) -> relu -> hi/lo
    mma_gemm_k<<<dim3(MTOT/128, 2), 256, GSMEM>>>(ahi, alo, whi + 0*65536, wlo + 0*65536,
                                                  fm_b1, (float*)0, bhi, blo, 2,
                                                  (__nv_bfloat16*)0, (__nv_bfloat16*)0, (float*)0, (float*)0);
    // fm2: -> relu fp32
    mma_gemm_k<<<dim3(MTOT/128, 2), 256, GSMEM>>>(bhi, blo, whi + 1*65536, wlo + 1*65536,
                                                  fm_b2, bufA, (__nv_bfloat16*)0, (__nv_bfloat16*)0, 1,
                                                  (__nv_bfloat16*)0, (__nv_bfloat16*)0, (float*)0, (float*)0);
    token_ln_k<<<MTOT/8, 256>>>(bufA, in_g, in_b);
    // K (y<2) and V (y>=2) fused in one launch
    mma_gemm_k<<<dim3(MTOT/128, 4), 256, GSMEM>>>(ahi, alo, whi + 2*65536, wlo + 2*65536,
                                                  k_b, bufC, (__nv_bfloat16*)0, (__nv_bfloat16*)0, 3,
                                                  whi + 3*65536, wlo + 3*65536, v_b, bufA);

    slots_init_k<<<256, 256>>>(eps_n, sl_loc, sl_lsc);

    for (int it = 0; it < 3; it++){
        slotln_q_k<<<BATCH, 256>>>(slot_g, slot_b, q_w, q_b);
        attn_k<<<dim3(64, BATCH), 256>>>();
        rowsum_k<<<BATCH*NSLOT, 256>>>();
        updpart_k<<<dim3(8, 2, BATCH), 128>>>();
        updred_k<<<256, 256>>>();
        gru_k<<<BATCH, 256>>>(gru_wih, gru_whh, gru_bih, gru_bhh,
                              pre_g, pre_b, st_w1, st_b1, st_w2, st_b2);
    }

    copy_out_k<<<256, 256>>>((float*)d_out);
}

// round 7
// speedup vs baseline: 1.0371x; 1.0371x over previous
#include <cuda_runtime.h>
#include <cuda_bf16.h>
#include <math.h>
#include <stdint.h>

#define BATCH 32
#define DIM 256
#define NTOK 4096
#define NSLOT 8
#define MTOT (BATCH*NTOK)

// ---------------- scratch (device globals; no runtime allocation) ----------------
__device__ float g_bufA[BATCH*NTOK*DIM];   // fm2 out / V
__device__ float g_bufC[BATCH*NTOK*DIM];   // K
__device__ __nv_bfloat16 g_ahi[MTOT*DIM];  // GEMM input planes (hi)
__device__ __nv_bfloat16 g_alo[MTOT*DIM];  // (lo)
__device__ __nv_bfloat16 g_bhi[MTOT*DIM];  // fm1 out planes
__device__ __nv_bfloat16 g_blo[MTOT*DIM];
__device__ float g_pos[NTOK*DIM];          // [t][d]
__device__ float g_posT[DIM*NTOK];         // [d][t]
__device__ float g_part[BATCH*256*2];
__device__ float g_stats[BATCH*2];
__device__ float g_attn[BATCH*NTOK*NSLOT]; // [b][t][s]
__device__ float g_psum[BATCH*NSLOT*8];    // [b][s][chunk] attn partial sums
__device__ float g_q[BATCH*NSLOT*DIM];
__device__ float g_updp[BATCH*8*NSLOT*DIM]; // [b][chunk][s][d]
__device__ float g_slots[BATCH*NSLOT*DIM];
__device__ __nv_bfloat16 g_whi[4*DIM*DIM]; // weights [N][K] bf16 hi
__device__ __nv_bfloat16 g_wlo[4*DIM*DIM]; // weights [N][K] bf16 lo

__device__ __forceinline__ float wred(float v){
    #pragma unroll
    for (int o = 16; o; o >>= 1) v += __shfl_xor_sync(0xffffffffu, v, o);
    return v;
}
__device__ __forceinline__ uint32_t smem_u32(const void* p){
    uint32_t a;
    asm("{ .reg .u64 t; cvta.to.shared.u64 t, %1; cvt.u32.u64 %0, t; }" : "=r"(a) : "l"(p));
    return a;
}
__device__ __forceinline__ void ldsm4(uint32_t* r, uint32_t addr){
    asm volatile("ldmatrix.sync.aligned.m8n8.x4.shared.b16 {%0,%1,%2,%3}, [%4];"
        : "=r"(r[0]), "=r"(r[1]), "=r"(r[2]), "=r"(r[3]) : "r"(addr));
}
__device__ __forceinline__ void mma16816(float* c, const uint32_t* a, const uint32_t* b){
    asm volatile("mma.sync.aligned.m16n8k16.row.col.f32.bf16.bf16.f32 "
        "{%0,%1,%2,%3}, {%4,%5,%6,%7}, {%8,%9}, {%0,%1,%2,%3};"
        : "+f"(c[0]), "+f"(c[1]), "+f"(c[2]), "+f"(c[3])
        : "r"(a[0]), "r"(a[1]), "r"(a[2]), "r"(a[3]), "r"(b[0]), "r"(b[1]));
}
__device__ __forceinline__ uint32_t sw64(uint32_t boff){
    return boff ^ ((boff >> 3) & 0x30);
}
__device__ __forceinline__ void cpa16(uint32_t s, const void* g){
    asm volatile("cp.async.cg.shared.global [%0], [%1], 16;" :: "r"(s), "l"(g));
}
__device__ __forceinline__ void cpa_commit(){
    asm volatile("cp.async.commit_group;");
}

// ---------------- weight prep: transpose [K,N]->[N,K], split hi/lo ----------------
__global__ void prep_w_k(const float* __restrict__ w, __nv_bfloat16* __restrict__ whi,
                         __nv_bfloat16* __restrict__ wlo){
    int idx = blockIdx.x*256 + threadIdx.x;   // n*256 + k
    int n = idx >> 8, k = idx & 255;
    float a = w[k*256 + n];
    __nv_bfloat16 h = __float2bfloat16(a);
    float r = a - __bfloat162float(h);
    whi[idx] = h;
    wlo[idx] = __float2bfloat16(r);
}

// ---------------- HMMA GEMM: C[M,256] = act(Ahl @ Whl + bias) ----------------
// CTA tile M=64 x N=256 (full width -> A read ONCE). 8 warps (2m x 4n), warp 32x64.
// K-chunk 32, double-buffered cp.async. smem 80KB, 2 CTAs/SM.
// mode: 0 = fp32 out, 1 = fp32 relu out, 2 = relu + bf16 hi/lo out
__global__ void __launch_bounds__(256, 2) mma_gemm_k(
        const __nv_bfloat16* __restrict__ Ahi, const __nv_bfloat16* __restrict__ Alo,
        const __nv_bfloat16* __restrict__ Whi, const __nv_bfloat16* __restrict__ Wlo,
        const float* __restrict__ bias,
        float* __restrict__ C,
        __nv_bfloat16* __restrict__ Chi, __nv_bfloat16* __restrict__ Clo,
        int mode){
    extern __shared__ char dsm[];
    __shared__ float s_bias[256];
    int tid = threadIdx.x;
    uint32_t raw = smem_u32(dsm);
    uint32_t sb = (raw + 1023) & ~1023u;
    // layout: AHI [0,8K) 2 bufs x 4K; ALO [8K,16K); BHI [16K,48K) 2 x 16K; BLO [48K,80K)
    uint32_t aAH = sb, aAL = sb + 8192, aBH = sb + 16384, aBL = sb + 49152;

    s_bias[tid] = bias[tid];

    size_t bm = (size_t)blockIdx.x * 64;
    int lane = tid & 31, wid = tid >> 5;
    int wm = wid & 1, wn = wid >> 1;    // 2(m) x 4(n)

    float acc[2][8][4] = {};

    auto prefetch = [&](int c, int buf){
        int k0 = c * 32;
        // A: 64 rows x 64B x 2 planes = 512 x 16B
        #pragma unroll
        for (int p = 0; p < 2; p++){
            int id = tid + p*256;
            int plane = id >> 8;
            int rem = id & 255;
            int r = rem >> 2, qc = rem & 3;
            uint32_t soff = (uint32_t)(buf*4096) + sw64((uint32_t)(r*64 + qc*16));
            const __nv_bfloat16* src = (plane ? Alo : Ahi) + (bm + r)*256 + k0 + qc*8;
            cpa16((plane ? aAL : aAH) + soff, src);
        }
        // B: 256 rows x 64B x 2 planes = 2048 x 16B
        #pragma unroll
        for (int p = 0; p < 8; p++){
            int id = tid + p*256;
            int plane = id >> 10;
            int rem = id & 1023;
            int r = rem >> 2, qc = rem & 3;
            uint32_t soff = (uint32_t)(buf*16384) + sw64((uint32_t)(r*64 + qc*16));
            const __nv_bfloat16* src = (plane ? Wlo : Whi) + (size_t)r*256 + k0 + qc*8;
            cpa16((plane ? aBL : aBH) + soff, src);
        }
    };

    prefetch(0, 0);
    cpa_commit();

    #pragma unroll 1
    for (int c = 0; c < 8; c++){
        int buf = c & 1;
        if (c < 7){
            prefetch(c+1, buf ^ 1);
            cpa_commit();
            asm volatile("cp.async.wait_group 1;");
        } else {
            asm volatile("cp.async.wait_group 0;");
        }
        __syncthreads();

        #pragma unroll
        for (int ks = 0; ks < 2; ks++){
            uint32_t Ah[2][4], Al[2][4];
            #pragma unroll
            for (int i = 0; i < 2; i++){
                uint32_t row = wm*32 + i*16 + (lane & 15);
                uint32_t sw = sw64(row*64 + ks*32 + (lane >> 4)*16);
                ldsm4(Ah[i], aAH + buf*4096 + sw);
                ldsm4(Al[i], aAL + buf*4096 + sw);
            }
            #pragma unroll
            for (int j2 = 0; j2 < 4; j2++){
                uint32_t row = wn*64 + j2*16 + (lane >> 4)*8 + (lane & 7);
                uint32_t sw = sw64(row*64 + ks*32 + ((lane >> 3) & 1)*16);
                uint32_t bh[4], bl[4];
                ldsm4(bh, aBH + buf*16384 + sw);
                ldsm4(bl, aBL + buf*16384 + sw);
                #pragma unroll
                for (int i = 0; i < 2; i++){
                    mma16816(acc[i][2*j2],   Ah[i], bh);
                    mma16816(acc[i][2*j2],   Ah[i], bl);
                    mma16816(acc[i][2*j2],   Al[i], bh);
                    mma16816(acc[i][2*j2+1], Ah[i], bh+2);
                    mma16816(acc[i][2*j2+1], Ah[i], bl+2);
                    mma16816(acc[i][2*j2+1], Al[i], bh+2);
                }
            }
        }
        __syncthreads();
    }

    int row0 = (int)bm + wm*32 + (lane >> 2);
    int col0 = wn*64 + 2*(lane & 3);
    #pragma unroll
    for (int i = 0; i < 2; i++){
        #pragma unroll
        for (int j = 0; j < 8; j++){
            int col = col0 + j*8;
            float b0 = s_bias[col], b1 = s_bias[col+1];
            float v00 = acc[i][j][0] + b0, v01 = acc[i][j][1] + b1;
            float v10 = acc[i][j][2] + b0, v11 = acc[i][j][3] + b1;
            if (mode >= 1){
                v00 = fmaxf(v00, 0.f); v01 = fmaxf(v01, 0.f);
                v10 = fmaxf(v10, 0.f); v11 = fmaxf(v11, 0.f);
            }
            size_t r0 = (size_t)(row0 + i*16)*256 + col;
            size_t r1 = r0 + 8*256;
            if (mode == 2){
                __nv_bfloat16 h00 = __float2bfloat16(v00), h01 = __float2bfloat16(v01);
                __nv_bfloat16 h10 = __float2bfloat16(v10), h11 = __float2bfloat16(v11);
                *(__nv_bfloat162*)&Chi[r0] = __halves2bfloat162(h00, h01);
                *(__nv_bfloat162*)&Chi[r1] = __halves2bfloat162(h10, h11);
                *(__nv_bfloat162*)&Clo[r0] = __halves2bfloat162(
                    __float2bfloat16(v00 - __bfloat162float(h00)),
                    __float2bfloat16(v01 - __bfloat162float(h01)));
                *(__nv_bfloat162*)&Clo[r1] = __halves2bfloat162(
                    __float2bfloat16(v10 - __bfloat162float(h10)),
                    __float2bfloat16(v11 - __bfloat162float(h11)));
            } else {
                float2 o0 = {v00, v01}, o1 = {v10, v11};
                *(float2*)&C[r0] = o0;
                *(float2*)&C[r1] = o1;
            }
        }
    }
}

// ---------------- positional embedding (both layouts) ----------------
__global__ void pos_k(const float* __restrict__ pw, const float* __restrict__ pb){
    int idx = blockIdx.x*256 + threadIdx.x;
    int t = idx >> 8, d = idx & 255;
    float gx = (float)(t >> 6) * (1.0f/63.0f);
    float gy = (float)(t & 63) * (1.0f/63.0f);
    float v = gx*pw[d] + gy*pw[256+d] + (1.f-gx)*pw[512+d] + (1.f-gy)*pw[768+d] + pb[d];
    g_pos[t*DIM + d] = v;
    g_posT[d*NTOK + t] = v;
}

// ---------------- whole-image LN stats (deterministic 2-stage) ----------------
__global__ void __launch_bounds__(256) stats_partial_k(const float* __restrict__ x){
    int b = blockIdx.y, p = blockIdx.x, tid = threadIdx.x;
    const float* xb = x + (size_t)b*(DIM*NTOK) + (size_t)p*NTOK;
    const float* pt = g_posT + (size_t)p*NTOK;
    float s = 0.f, sq = 0.f;
    #pragma unroll
    for (int j = 0; j < 16; j++){
        float v = xb[tid + j*256] + pt[tid + j*256];
        s += v; sq += v*v;
    }
    __shared__ float ss[256], sqs[256];
    ss[tid] = s; sqs[tid] = sq; __syncthreads();
    for (int st = 128; st; st >>= 1){
        if (tid < st){ ss[tid] += ss[tid+st]; sqs[tid] += sqs[tid+st]; }
        __syncthreads();
    }
    if (!tid){ g_part[(b*256+p)*2] = ss[0]; g_part[(b*256+p)*2+1] = sqs[0]; }
}

__global__ void stats_final_k(){
    int b = blockIdx.x, tid = threadIdx.x;
    __shared__ float ss[256], sqs[256];
    ss[tid]  = g_part[(b*256+tid)*2];
    sqs[tid] = g_part[(b*256+tid)*2+1];
    __syncthreads();
    for (int st = 128; st; st >>= 1){
        if (tid < st){ ss[tid] += ss[tid+st]; sqs[tid] += sqs[tid+st]; }
        __syncthreads();
    }
    if (!tid){
        const float invN = 1.0f/1048576.0f;
        float m = ss[0]*invN;
        float var = sqs[0]*invN - m*m;
        g_stats[b*2] = m;
        g_stats[b*2+1] = rsqrtf(var + 1e-5f);
    }
}

// ---------------- normalize + transpose -> hi/lo token planes ----------------
__global__ void __launch_bounds__(256) norm_tok_k(const float* __restrict__ x,
                                                  const float* __restrict__ eg,
                                                  const float* __restrict__ eb){
    __shared__ float sh[32][33];
    int b = blockIdx.z;
    int d0 = blockIdx.y*32, t0 = blockIdx.x*32;
    int tx = threadIdx.x, ty = threadIdx.y;
    float mean = g_stats[b*2], rstd = g_stats[b*2+1];
    const float* xb = x + (size_t)b*(DIM*NTOK);
    #pragma unroll
    for (int r = 0; r < 4; r++)
        sh[ty+8*r][tx] = xb[(size_t)(d0+ty+8*r)*NTOK + t0 + tx];
    __syncthreads();
    size_t ob = (size_t)b*(NTOK*DIM);
    #pragma unroll
    for (int r = 0; r < 4; r++){
        int trow = t0 + ty + 8*r;
        int dcol = d0 + tx;
        int pi = trow*DIM + dcol;
        float v = sh[tx][ty+8*r] + g_pos[pi];
        float o = (v - mean)*rstd*eg[pi] + eb[pi];
        __nv_bfloat16 h = __float2bfloat16(o);
        g_ahi[ob + pi] = h;
        g_alo[ob + pi] = __float2bfloat16(o - __bfloat162float(h));
    }
}

// ---------------- per-token LayerNorm -> hi/lo planes ----------------
__global__ void __launch_bounds__(256) token_ln_k(const float* __restrict__ A,
                                                  const float* __restrict__ g,
                                                  const float* __restrict__ be){
    int warp = threadIdx.x >> 5, lane = threadIdx.x & 31;
    size_t row = (size_t)blockIdx.x*8 + warp;
    const float4* r4 = (const float4*)(A + row*DIM);
    float4 v0 = r4[lane], v1 = r4[lane+32];
    float s  = v0.x+v0.y+v0.z+v0.w + v1.x+v1.y+v1.z+v1.w;
    float sq = v0.x*v0.x+v0.y*v0.y+v0.z*v0.z+v0.w*v0.w
             + v1.x*v1.x+v1.y*v1.y+v1.z*v1.z+v1.w*v1.w;
    s = wred(s); sq = wred(sq);
    float m = s*(1.0f/256.0f);
    float var = sq*(1.0f/256.0f) - m*m;
    float rs = rsqrtf(var + 1e-5f);
    const float4* g4 = (const float4*)g;
    const float4* b4 = (const float4*)be;
    float4 ga = g4[lane], gb = g4[lane+32], ba = b4[lane], bb = b4[lane+32];
    float o[8];
    o[0] = (v0.x-m)*rs*ga.x + ba.x; o[1] = (v0.y-m)*rs*ga.y + ba.y;
    o[2] = (v0.z-m)*rs*ga.z + ba.z; o[3] = (v0.w-m)*rs*ga.w + ba.w;
    o[4] = (v1.x-m)*rs*gb.x + bb.x; o[5] = (v1.y-m)*rs*gb.y + bb.y;
    o[6] = (v1.z-m)*rs*gb.z + bb.z; o[7] = (v1.w-m)*rs*gb.w + bb.w;
    __nv_bfloat162* H2 = (__nv_bfloat162*)(g_ahi + row*DIM);
    __nv_bfloat162* L2 = (__nv_bfloat162*)(g_alo + row*DIM);
    #pragma unroll
    for (int h2 = 0; h2 < 2; h2++){
        #pragma unroll
        for (int q2 = 0; q2 < 2; q2++){
            float a0 = o[h2*4 + q2*2], a1 = o[h2*4 + q2*2 + 1];
            __nv_bfloat16 hh0 = __float2bfloat16(a0), hh1 = __float2bfloat16(a1);
            int pidx = h2*64 + lane*2 + q2;
            H2[pidx] = __halves2bfloat162(hh0, hh1);
            L2[pidx] = __halves2bfloat162(
                __float2bfloat16(a0 - __bfloat162float(hh0)),
                __float2bfloat16(a1 - __bfloat162float(hh1)));
        }
    }
}

// ---------------- slots init ----------------
__global__ void slots_init_k(const float* __restrict__ eps, const float* __restrict__ loc,
                             const float* __restrict__ lsc){
    int idx = blockIdx.x*256 + threadIdx.x;
    int d = idx & 255;
    g_slots[idx] = loc[d] + expf(lsc[d]) * eps[idx];
}

// ---------------- slot LN + Q projection ----------------
__global__ void __launch_bounds__(256) slotln_q_k(const float* __restrict__ sg,
                                                  const float* __restrict__ sb,
                                                  const float* __restrict__ qw,
                                                  const float* __restrict__ qb){
    __shared__ float sn[8][256];
    int b = blockIdx.x, tid = threadIdx.x, warp = tid >> 5, lane = tid & 31;
    const float* sl = g_slots + (b*8 + warp)*256;
    float v[8]; float s = 0.f, sq = 0.f;
    #pragma unroll
    for (int i = 0; i < 8; i++){ v[i] = sl[lane + 32*i]; s += v[i]; sq += v[i]*v[i]; }
    s = wred(s); sq = wred(sq);
    float m = s*(1.f/256.f), var = sq*(1.f/256.f) - m*m, rs = rsqrtf(var + 1e-5f);
    #pragma unroll
    for (int i = 0; i < 8; i++){
        int d = lane + 32*i;
        sn[warp][d] = (v[i]-m)*rs*sg[d] + sb[d];
    }
    __syncthreads();
    int c = tid;
    float acc[8] = {};
    for (int k = 0; k < 256; k++){
        float w = qw[k*256 + c];
        #pragma unroll
        for (int s2 = 0; s2 < 8; s2++) acc[s2] += sn[s2][k]*w;
    }
    float bq = qb[c];
    #pragma unroll
    for (int s2 = 0; s2 < 8; s2++) g_q[(b*8+s2)*256 + c] = acc[s2] + bq;
}

// ---------------- dots + softmax over slots (warp per token) ----------------
__global__ void __launch_bounds__(256) attn_k(){
    __shared__ __align__(16) float qs[2048];
    int b = blockIdx.y, tid = threadIdx.x;
    #pragma unroll
    for (int i = 0; i < 8; i++) qs[tid + 256*i] = g_q[b*2048 + tid + 256*i];
    __syncthreads();
    int warp = tid >> 5, lane = tid & 31;
    const float4* K4 = (const float4*)(g_bufC + (size_t)b*NTOK*DIM);
    int t0 = blockIdx.x*64 + warp*8;
    for (int tt = 0; tt < 8; tt++){
        int t = t0 + tt;
        float4 k0 = K4[t*64 + lane];
        float4 k1 = K4[t*64 + 32 + lane];
        float acc[8];
        #pragma unroll
        for (int s = 0; s < 8; s++){
            const float4* q4 = (const float4*)&qs[s*256];
            float4 q0 = q4[lane], q1 = q4[lane+32];
            acc[s] = k0.x*q0.x + k0.y*q0.y + k0.z*q0.z + k0.w*q0.w
                   + k1.x*q1.x + k1.y*q1.y + k1.z*q1.z + k1.w*q1.w;
        }
        #pragma unroll
        for (int s = 0; s < 8; s++) acc[s] = wred(acc[s]) * 0.0625f;
        float mx = acc[0];
        #pragma unroll
        for (int s = 1; s < 8; s++) mx = fmaxf(mx, acc[s]);
        float e[8], sum = 0.f;
        #pragma unroll
        for (int s = 0; s < 8; s++){ e[s] = expf(acc[s] - mx); sum += e[s]; }
        float inv = 1.f/sum;
        if (lane < 8)
            g_attn[((size_t)b*NTOK + t)*8 + lane] = e[lane]*inv + 1e-8f;
    }
}

// ---------------- upd partials = attn @ V  (chunked, deterministic) + attn rowsums ----------------
__global__ void __launch_bounds__(128) updpart_k(){
    int b = blockIdx.z, dt = blockIdx.y, c = blockIdx.x;
    int tid = threadIdx.x;
    int d = dt*128 + tid;
    __shared__ float as[8][132];
    float acc[8] = {};
    float ps = 0.f;
    const float* V = g_bufA + (size_t)b*NTOK*DIM;
    for (int tb = c*512; tb < c*512 + 512; tb += 128){
        for (int i = tid; i < 1024; i += 128){
            int s = i & 7, j = i >> 3;
            as[s][j] = g_attn[((size_t)b*NTOK + tb + j)*8 + s];
        }
        __syncthreads();
        if (dt == 0 && tid < 8){
            #pragma unroll 4
            for (int j = 0; j < 128; j++) ps += as[tid][j];
        }
        #pragma unroll 4
        for (int j = 0; j < 128; j++){
            float vv = V[(size_t)(tb+j)*256 + d];
            #pragma unroll
            for (int s = 0; s < 8; s++) acc[s] += as[s][j]*vv;
        }
        __syncthreads();
    }
    #pragma unroll
    for (int s = 0; s < 8; s++)
        g_updp[(((b*8)+c)*8 + s)*256 + d] = acc[s];
    if (dt == 0 && tid < 8)
        g_psum[(b*8 + tid)*8 + c] = ps;
}

// ---------------- GRU + pre-LN + residual MLP (one block per batch) ----------------
__global__ void __launch_bounds__(256) gru_k(const float* __restrict__ wih, const float* __restrict__ whh,
                                             const float* __restrict__ bih, const float* __restrict__ bhh,
                                             const float* __restrict__ pg,  const float* __restrict__ pb,
                                             const float* __restrict__ w1,  const float* __restrict__ b1,
                                             const float* __restrict__ w2,  const float* __restrict__ b2){
    __shared__ float su[8][256];
    __shared__ float sp[8][256];
    __shared__ float sf[8][256];
    __shared__ float r_s[8];
    int b = blockIdx.x, tid = threadIdx.x, warp = tid >> 5, lane = tid & 31;
    if (tid < 8){
        float s = 0.f;
        #pragma unroll
        for (int c = 0; c < 8; c++) s += g_psum[(b*8 + tid)*8 + c];
        r_s[tid] = 1.f/s;
    }
    __syncthreads();
    #pragma unroll
    for (int i = 0; i < 8; i++){
        float s = 0.f;
        #pragma unroll
        for (int c = 0; c < 8; c++) s += g_updp[(((b*8)+c)*8 + i)*256 + tid];
        su[i][tid] = s * r_s[i];
        sp[i][tid] = g_slots[b*2048 + i*256 + tid];
    }
    __syncthreads();
    int c = tid;
    float gir[8] = {}, giz[8] = {}, gin[8] = {};
    float ghr[8] = {}, ghz[8] = {}, ghn[8] = {};
    for (int k = 0; k < 256; k++){
        float wi0 = wih[k*768 + c], wi1 = wih[k*768 + 256 + c], wi2 = wih[k*768 + 512 + c];
        float wh0 = whh[k*768 + c], wh1 = whh[k*768 + 256 + c], wh2 = whh[k*768 + 512 + c];
        #pragma unroll
        for (int s = 0; s < 8; s++){
            float us = su[s][k], psv = sp[s][k];
            gir[s] += us*wi0; giz[s] += us*wi1; gin[s] += us*wi2;
            ghr[s] += psv*wh0; ghz[s] += psv*wh1; ghn[s] += psv*wh2;
        }
    }
    float br = bih[c], bz = bih[256+c], bn_ = bih[512+c];
    float cr = bhh[c], cz = bhh[256+c], cn  = bhh[512+c];
    #pragma unroll
    for (int s = 0; s < 8; s++){
        float r = 1.f/(1.f + expf(-(gir[s]+br + ghr[s]+cr)));
        float z = 1.f/(1.f + expf(-(giz[s]+bz + ghz[s]+cz)));
        float n = tanhf(gin[s]+bn_ + r*(ghn[s]+cn));
        sf[s][c] = (1.f - z)*n + z*sp[s][c];
    }
    __syncthreads();
    {
        float v[8], s_ = 0.f, sq = 0.f;
        #pragma unroll
        for (int i = 0; i < 8; i++){ v[i] = sf[warp][lane+32*i]; s_ += v[i]; sq += v[i]*v[i]; }
        s_ = wred(s_); sq = wred(sq);
        float m = s_*(1.f/256.f), var = sq*(1.f/256.f) - m*m, rs = rsqrtf(var + 1e-5f);
        #pragma unroll
        for (int i = 0; i < 8; i++){
            int d = lane + 32*i;
            su[warp][d] = (v[i]-m)*rs*pg[d] + pb[d];
        }
    }
    __syncthreads();
    {
        float acc[8] = {};
        for (int k = 0; k < 256; k++){
            float w = w1[k*256 + c];
            #pragma unroll
            for (int s = 0; s < 8; s++) acc[s] += su[s][k]*w;
        }
        float bb = b1[c];
        #pragma unroll
        for (int s = 0; s < 8; s++) sp[s][c] = fmaxf(acc[s] + bb, 0.f);
    }
    __syncthreads();
    {
        float acc[8] = {};
        for (int k = 0; k < 256; k++){
            float w = w2[k*256 + c];
            #pragma unroll
            for (int s = 0; s < 8; s++) acc[s] += sp[s][k]*w;
        }
        float bb = b2[c];
        #pragma unroll
        for (int s = 0; s < 8; s++)
            g_slots[b*2048 + s*256 + c] = sf[s][c] + fmaxf(acc[s] + bb, 0.f);
    }
}

__global__ void copy_out_k(float* __restrict__ out){
    int idx = blockIdx.x*256 + threadIdx.x;
    out[idx] = g_slots[idx];
}

// ---------------- launch ----------------
extern "C" void kernel_launch(void* const* d_in, const int* in_sizes, int n_in,
                              void* d_out, int out_size){
    const float* x       = (const float*)d_in[0];
    const float* eps_n   = (const float*)d_in[1];
    const float* pos_w   = (const float*)d_in[2];
    const float* pos_b   = (const float*)d_in[3];
    const float* enc_g   = (const float*)d_in[4];
    const float* enc_b   = (const float*)d_in[5];
    const float* fm_w1   = (const float*)d_in[6];
    const float* fm_b1   = (const float*)d_in[7];
    const float* fm_w2   = (const float*)d_in[8];
    const float* fm_b2   = (const float*)d_in[9];
    const float* in_g    = (const float*)d_in[10];
    const float* in_b    = (const float*)d_in[11];
    const float* q_w     = (const float*)d_in[12];
    const float* q_b     = (const float*)d_in[13];
    const float* k_w     = (const float*)d_in[14];
    const float* k_b     = (const float*)d_in[15];
    const float* v_w     = (const float*)d_in[16];
    const float* v_b     = (const float*)d_in[17];
    const float* gru_wih = (const float*)d_in[18];
    const float* gru_whh = (const float*)d_in[19];
    const float* gru_bih = (const float*)d_in[20];
    const float* gru_bhh = (const float*)d_in[21];
    const float* pre_g   = (const float*)d_in[22];
    const float* pre_b   = (const float*)d_in[23];
    const float* st_w1   = (const float*)d_in[24];
    const float* st_b1   = (const float*)d_in[25];
    const float* st_w2   = (const float*)d_in[26];
    const float* st_b2   = (const float*)d_in[27];
    const float* slot_g  = (const float*)d_in[28];
    const float* slot_b  = (const float*)d_in[29];
    const float* sl_loc  = (const float*)d_in[30];
    const float* sl_lsc  = (const float*)d_in[31];

    float *bufA, *bufC;
    __nv_bfloat16 *whi, *wlo, *ahi, *alo, *bhi, *blo;
    cudaGetSymbolAddress((void**)&bufA, g_bufA);
    cudaGetSymbolAddress((void**)&bufC, g_bufC);
    cudaGetSymbolAddress((void**)&whi, g_whi);
    cudaGetSymbolAddress((void**)&wlo, g_wlo);
    cudaGetSymbolAddress((void**)&ahi, g_ahi);
    cudaGetSymbolAddress((void**)&alo, g_alo);
    cudaGetSymbolAddress((void**)&bhi, g_bhi);
    cudaGetSymbolAddress((void**)&blo, g_blo);

    const int GSMEM = 82944;   // 80KB + align slack
    cudaFuncSetAttribute(mma_gemm_k, cudaFuncAttributeMaxDynamicSharedMemorySize, GSMEM);

    prep_w_k<<<256, 256>>>(fm_w1, whi + 0*65536, wlo + 0*65536);
    prep_w_k<<<256, 256>>>(fm_w2, whi + 1*65536, wlo + 1*65536);
    prep_w_k<<<256, 256>>>(k_w,   whi + 2*65536, wlo + 2*65536);
    prep_w_k<<<256, 256>>>(v_w,   whi + 3*65536, wlo + 3*65536);

    pos_k<<<4096, 256>>>(pos_w, pos_b);
    stats_partial_k<<<dim3(256, BATCH), 256>>>(x);
    stats_final_k<<<BATCH, 256>>>();
    norm_tok_k<<<dim3(128, 8, BATCH), dim3(32, 8)>>>(x, enc_g, enc_b);

    // fm1: tokens(hi/lo) -> relu -> hi/lo
    mma_gemm_k<<<MTOT/64, 256, GSMEM>>>(ahi, alo, whi + 0*65536, wlo + 0*65536,
                                        fm_b1, (float*)0, bhi, blo, 2);
    // fm2: -> relu fp32
    mma_gemm_k<<<MTOT/64, 256, GSMEM>>>(bhi, blo, whi + 1*65536, wlo + 1*65536,
                                        fm_b2, bufA, (__nv_bfloat16*)0, (__nv_bfloat16*)0, 1);
    token_ln_k<<<MTOT/8, 256>>>(bufA, in_g, in_b);
    // K
    mma_gemm_k<<<MTOT/64, 256, GSMEM>>>(ahi, alo, whi + 2*65536, wlo + 2*65536,
                                        k_b, bufC, (__nv_bfloat16*)0, (__nv_bfloat16*)0, 0);
    // V
    mma_gemm_k<<<MTOT/64, 256, GSMEM>>>(ahi, alo, whi + 3*65536, wlo + 3*65536,
                                        v_b, bufA, (__nv_bfloat16*)0, (__nv_bfloat16*)0, 0);

    slots_init_k<<<256, 256>>>(eps_n, sl_loc, sl_lsc);

    for (int it = 0; it < 3; it++){
        slotln_q_k<<<BATCH, 256>>>(slot_g, slot_b, q_w, q_b);
        attn_k<<<dim3(64, BATCH), 256>>>();
        updpart_k<<<dim3(8, 2, BATCH), 128>>>();
        gru_k<<<BATCH, 256>>>(gru_wih, gru_whh, gru_bih, gru_bhh,
                              pre_g, pre_b, st_w1, st_b1, st_w2, st_b2);
    }

    copy_out_k<<<256, 256>>>((float*)d_out);
}

// round 8
// speedup vs baseline: 1.1180x; 1.0780x over previous
#include <cuda_runtime.h>
#include <cuda_fp16.h>
#include <math.h>
#include <stdint.h>

#define BATCH 32
#define DIM 256
#define NTOK 4096
#define NSLOT 8
#define MTOT (BATCH*NTOK)

// ---------------- scratch (device globals; no runtime allocation) ----------------
__device__ float g_bufA[BATCH*NTOK*DIM];   // fm2 out / V
__device__ float g_bufC[BATCH*NTOK*DIM];   // K
__device__ __half g_a16[MTOT*DIM];         // GEMM activation plane (fp16)
__device__ __half g_b16[MTOT*DIM];         // fm1 out plane (fp16)
__device__ float g_pos[NTOK*DIM];          // [t][d]
__device__ float g_posT[DIM*NTOK];         // [d][t]
__device__ float g_part[BATCH*256*2];
__device__ float g_stats[BATCH*2];
__device__ float g_attn[BATCH*NTOK*NSLOT]; // [b][t][s]
__device__ float g_psum[BATCH*NSLOT*8];    // [b][s][chunk] attn partial sums
__device__ float g_q[BATCH*NSLOT*DIM];
__device__ float g_updp[BATCH*8*NSLOT*DIM]; // [b][chunk][s][d]
__device__ float g_slots[BATCH*NSLOT*DIM];
__device__ __half g_whi[4*DIM*DIM];        // weights [N][K] fp16 hi
__device__ __half g_wlo[4*DIM*DIM];        // weights [N][K] fp16 lo

__device__ __forceinline__ float wred(float v){
    #pragma unroll
    for (int o = 16; o; o >>= 1) v += __shfl_xor_sync(0xffffffffu, v, o);
    return v;
}
__device__ __forceinline__ uint32_t smem_u32(const void* p){
    uint32_t a;
    asm("{ .reg .u64 t; cvta.to.shared.u64 t, %1; cvt.u32.u64 %0, t; }" : "=r"(a) : "l"(p));
    return a;
}
__device__ __forceinline__ void ldsm4(uint32_t* r, uint32_t addr){
    asm volatile("ldmatrix.sync.aligned.m8n8.x4.shared.b16 {%0,%1,%2,%3}, [%4];"
        : "=r"(r[0]), "=r"(r[1]), "=r"(r[2]), "=r"(r[3]) : "r"(addr));
}
__device__ __forceinline__ void mma16816(float* c, const uint32_t* a, const uint32_t* b){
    asm volatile("mma.sync.aligned.m16n8k16.row.col.f32.f16.f16.f32 "
        "{%0,%1,%2,%3}, {%4,%5,%6,%7}, {%8,%9}, {%0,%1,%2,%3};"
        : "+f"(c[0]), "+f"(c[1]), "+f"(c[2]), "+f"(c[3])
        : "r"(a[0]), "r"(a[1]), "r"(a[2]), "r"(a[3]), "r"(b[0]), "r"(b[1]));
}
__device__ __forceinline__ uint32_t sw64(uint32_t boff){
    return boff ^ ((boff >> 3) & 0x30);
}
__device__ __forceinline__ void cpa16(uint32_t s, const void* g){
    asm volatile("cp.async.cg.shared.global [%0], [%1], 16;" :: "r"(s), "l"(g));
}
__device__ __forceinline__ void cpa_commit(){
    asm volatile("cp.async.commit_group;");
}

// ---------------- weight prep: transpose [K,N]->[N,K], split fp16 hi/lo ----------------
__global__ void prep_w_k(const float* __restrict__ w, __half* __restrict__ whi,
                         __half* __restrict__ wlo){
    int idx = blockIdx.x*256 + threadIdx.x;   // n*256 + k
    int n = idx >> 8, k = idx & 255;
    float a = w[k*256 + n];
    __half h = __float2half_rn(a);
    float r = a - __half2float(h);
    whi[idx] = h;
    wlo[idx] = __float2half_rn(r);
}

// ---------------- HMMA GEMM: C[M,256] = act(A16 @ (Whi+Wlo) + bias) ----------------
// CTA tile M=64 x N=256 (A read once). 8 warps (2m x 4n), warp 32x64.
// K-chunk 32, double-buffered cp.async. smem 72KB, 2 CTAs/SM.
// mode: 0 = fp32 out, 1 = fp32 relu out, 2 = relu + fp16 out
__global__ void __launch_bounds__(256, 2) mma_gemm_k(
        const __half* __restrict__ A16,
        const __half* __restrict__ Whi, const __half* __restrict__ Wlo,
        const float* __restrict__ bias,
        float* __restrict__ C,
        __half* __restrict__ C16,
        int mode){
    extern __shared__ char dsm[];
    __shared__ float s_bias[256];
    int tid = threadIdx.x;
    uint32_t raw = smem_u32(dsm);
    uint32_t sb = (raw + 1023) & ~1023u;
    // layout: A [0,8K) 2 bufs x 4K; BHI [8K,40K) 2 x 16K; BLO [40K,72K)
    uint32_t aA = sb, aBH = sb + 8192, aBL = sb + 40960;

    s_bias[tid] = bias[tid];

    size_t bm = (size_t)blockIdx.x * 64;
    int lane = tid & 31, wid = tid >> 5;
    int wm = wid & 1, wn = wid >> 1;    // 2(m) x 4(n)

    float acc[2][8][4] = {};

    auto prefetch = [&](int c, int buf){
        int k0 = c * 32;
        // A: 64 rows x 64B = 256 x 16B
        {
            int r = tid >> 2, qc = tid & 3;
            uint32_t soff = (uint32_t)(buf*4096) + sw64((uint32_t)(r*64 + qc*16));
            cpa16(aA + soff, A16 + (bm + r)*256 + k0 + qc*8);
        }
        // B: 2 planes x 256 rows x 4 = 2048 x 16B
        #pragma unroll
        for (int p = 0; p < 8; p++){
            int id = tid + p*256;
            int plane = id >> 10;
            int rem = id & 1023;
            int r = rem >> 2, qc = rem & 3;
            uint32_t soff = (uint32_t)(buf*16384) + sw64((uint32_t)(r*64 + qc*16));
            const __half* src = (plane ? Wlo : Whi) + (size_t)r*256 + k0 + qc*8;
            cpa16((plane ? aBL : aBH) + soff, src);
        }
    };

    prefetch(0, 0);
    cpa_commit();

    #pragma unroll 1
    for (int c = 0; c < 8; c++){
        int buf = c & 1;
        if (c < 7){
            prefetch(c+1, buf ^ 1);
            cpa_commit();
            asm volatile("cp.async.wait_group 1;");
        } else {
            asm volatile("cp.async.wait_group 0;");
        }
        __syncthreads();

        #pragma unroll
        for (int ks = 0; ks < 2; ks++){
            uint32_t Ah[2][4];
            #pragma unroll
            for (int i = 0; i < 2; i++){
                uint32_t row = wm*32 + i*16 + (lane & 15);
                uint32_t sw = sw64(row*64 + ks*32 + (lane >> 4)*16);
                ldsm4(Ah[i], aA + buf*4096 + sw);
            }
            #pragma unroll
            for (int j2 = 0; j2 < 4; j2++){
                uint32_t row = wn*64 + j2*16 + (lane >> 4)*8 + (lane & 7);
                uint32_t sw = sw64(row*64 + ks*32 + ((lane >> 3) & 1)*16);
                uint32_t bh[4], bl[4];
                ldsm4(bh, aBH + buf*16384 + sw);
                ldsm4(bl, aBL + buf*16384 + sw);
                #pragma unroll
                for (int i = 0; i < 2; i++){
                    mma16816(acc[i][2*j2],   Ah[i], bh);
                    mma16816(acc[i][2*j2],   Ah[i], bl);
                    mma16816(acc[i][2*j2+1], Ah[i], bh+2);
                    mma16816(acc[i][2*j2+1], Ah[i], bl+2);
                }
            }
        }
        __syncthreads();
    }

    int row0 = (int)bm + wm*32 + (lane >> 2);
    int col0 = wn*64 + 2*(lane & 3);
    #pragma unroll
    for (int i = 0; i < 2; i++){
        #pragma unroll
        for (int j = 0; j < 8; j++){
            int col = col0 + j*8;
            float b0 = s_bias[col], b1 = s_bias[col+1];
            float v00 = acc[i][j][0] + b0, v01 = acc[i][j][1] + b1;
            float v10 = acc[i][j][2] + b0, v11 = acc[i][j][3] + b1;
            if (mode >= 1){
                v00 = fmaxf(v00, 0.f); v01 = fmaxf(v01, 0.f);
                v10 = fmaxf(v10, 0.f); v11 = fmaxf(v11, 0.f);
            }
            size_t r0 = (size_t)(row0 + i*16)*256 + col;
            size_t r1 = r0 + 8*256;
            if (mode == 2){
                *(__half2*)&C16[r0] = __halves2half2(__float2half_rn(v00), __float2half_rn(v01));
                *(__half2*)&C16[r1] = __halves2half2(__float2half_rn(v10), __float2half_rn(v11));
            } else {
                float2 o0 = {v00, v01}, o1 = {v10, v11};
                *(float2*)&C[r0] = o0;
                *(float2*)&C[r1] = o1;
            }
        }
    }
}

// ---------------- positional embedding (both layouts) ----------------
__global__ void pos_k(const float* __restrict__ pw, const float* __restrict__ pb){
    int idx = blockIdx.x*256 + threadIdx.x;
    int t = idx >> 8, d = idx & 255;
    float gx = (float)(t >> 6) * (1.0f/63.0f);
    float gy = (float)(t & 63) * (1.0f/63.0f);
    float v = gx*pw[d] + gy*pw[256+d] + (1.f-gx)*pw[512+d] + (1.f-gy)*pw[768+d] + pb[d];
    g_pos[t*DIM + d] = v;
    g_posT[d*NTOK + t] = v;
}

// ---------------- whole-image LN stats (deterministic 2-stage) ----------------
__global__ void __launch_bounds__(256) stats_partial_k(const float* __restrict__ x){
    int b = blockIdx.y, p = blockIdx.x, tid = threadIdx.x;
    const float* xb = x + (size_t)b*(DIM*NTOK) + (size_t)p*NTOK;
    const float* pt = g_posT + (size_t)p*NTOK;
    float s = 0.f, sq = 0.f;
    #pragma unroll
    for (int j = 0; j < 16; j++){
        float v = xb[tid + j*256] + pt[tid + j*256];
        s += v; sq += v*v;
    }
    __shared__ float ss[256], sqs[256];
    ss[tid] = s; sqs[tid] = sq; __syncthreads();
    for (int st = 128; st; st >>= 1){
        if (tid < st){ ss[tid] += ss[tid+st]; sqs[tid] += sqs[tid+st]; }
        __syncthreads();
    }
    if (!tid){ g_part[(b*256+p)*2] = ss[0]; g_part[(b*256+p)*2+1] = sqs[0]; }
}

__global__ void stats_final_k(){
    int b = blockIdx.x, tid = threadIdx.x;
    __shared__ float ss[256], sqs[256];
    ss[tid]  = g_part[(b*256+tid)*2];
    sqs[tid] = g_part[(b*256+tid)*2+1];
    __syncthreads();
    for (int st = 128; st; st >>= 1){
        if (tid < st){ ss[tid] += ss[tid+st]; sqs[tid] += sqs[tid+st]; }
        __syncthreads();
    }
    if (!tid){
        const float invN = 1.0f/1048576.0f;
        float m = ss[0]*invN;
        float var = sqs[0]*invN - m*m;
        g_stats[b*2] = m;
        g_stats[b*2+1] = rsqrtf(var + 1e-5f);
    }
}

// ---------------- normalize + transpose -> fp16 token plane ----------------
__global__ void __launch_bounds__(256) norm_tok_k(const float* __restrict__ x,
                                                  const float* __restrict__ eg,
                                                  const float* __restrict__ eb){
    __shared__ float sh[32][33];
    int b = blockIdx.z;
    int d0 = blockIdx.y*32, t0 = blockIdx.x*32;
    int tx = threadIdx.x, ty = threadIdx.y;
    float mean = g_stats[b*2], rstd = g_stats[b*2+1];
    const float* xb = x + (size_t)b*(DIM*NTOK);
    #pragma unroll
    for (int r = 0; r < 4; r++)
        sh[ty+8*r][tx] = xb[(size_t)(d0+ty+8*r)*NTOK + t0 + tx];
    __syncthreads();
    size_t ob = (size_t)b*(NTOK*DIM);
    #pragma unroll
    for (int r = 0; r < 4; r++){
        int trow = t0 + ty + 8*r;
        int dcol = d0 + tx;
        int pi = trow*DIM + dcol;
        float v = sh[tx][ty+8*r] + g_pos[pi];
        float o = (v - mean)*rstd*eg[pi] + eb[pi];
        g_a16[ob + pi] = __float2half_rn(o);
    }
}

// ---------------- per-token LayerNorm -> fp16 plane ----------------
__global__ void __launch_bounds__(256) token_ln_k(const float* __restrict__ A,
                                                  const float* __restrict__ g,
                                                  const float* __restrict__ be){
    int warp = threadIdx.x >> 5, lane = threadIdx.x & 31;
    size_t row = (size_t)blockIdx.x*8 + warp;
    const float4* r4 = (const float4*)(A + row*DIM);
    float4 v0 = r4[lane], v1 = r4[lane+32];
    float s  = v0.x+v0.y+v0.z+v0.w + v1.x+v1.y+v1.z+v1.w;
    float sq = v0.x*v0.x+v0.y*v0.y+v0.z*v0.z+v0.w*v0.w
             + v1.x*v1.x+v1.y*v1.y+v1.z*v1.z+v1.w*v1.w;
    s = wred(s); sq = wred(sq);
    float m = s*(1.0f/256.0f);
    float var = sq*(1.0f/256.0f) - m*m;
    float rs = rsqrtf(var + 1e-5f);
    const float4* g4 = (const float4*)g;
    const float4* b4 = (const float4*)be;
    float4 ga = g4[lane], gb = g4[lane+32], ba = b4[lane], bb = b4[lane+32];
    float o[8];
    o[0] = (v0.x-m)*rs*ga.x + ba.x; o[1] = (v0.y-m)*rs*ga.y + ba.y;
    o[2] = (v0.z-m)*rs*ga.z + ba.z; o[3] = (v0.w-m)*rs*ga.w + ba.w;
    o[4] = (v1.x-m)*rs*gb.x + bb.x; o[5] = (v1.y-m)*rs*gb.y + bb.y;
    o[6] = (v1.z-m)*rs*gb.z + bb.z; o[7] = (v1.w-m)*rs*gb.w + bb.w;
    __half2* H2 = (__half2*)(g_a16 + row*DIM);
    #pragma unroll
    for (int h2 = 0; h2 < 2; h2++){
        #pragma unroll
        for (int q2 = 0; q2 < 2; q2++){
            float a0 = o[h2*4 + q2*2], a1 = o[h2*4 + q2*2 + 1];
            H2[h2*64 + lane*2 + q2] = __halves2half2(__float2half_rn(a0), __float2half_rn(a1));
        }
    }
}

// ---------------- slots init ----------------
__global__ void slots_init_k(const float* __restrict__ eps, const float* __restrict__ loc,
                             const float* __restrict__ lsc){
    int idx = blockIdx.x*256 + threadIdx.x;
    int d = idx & 255;
    g_slots[idx] = loc[d] + expf(lsc[d]) * eps[idx];
}

// ---------------- slot LN + Q projection ----------------
__global__ void __launch_bounds__(256) slotln_q_k(const float* __restrict__ sg,
                                                  const float* __restrict__ sb,
                                                  const float* __restrict__ qw,
                                                  const float* __restrict__ qb){
    __shared__ float sn[8][256];
    int b = blockIdx.x, tid = threadIdx.x, warp = tid >> 5, lane = tid & 31;
    const float* sl = g_slots + (b*8 + warp)*256;
    float v[8]; float s = 0.f, sq = 0.f;
    #pragma unroll
    for (int i = 0; i < 8; i++){ v[i] = sl[lane + 32*i]; s += v[i]; sq += v[i]*v[i]; }
    s = wred(s); sq = wred(sq);
    float m = s*(1.f/256.f), var = sq*(1.f/256.f) - m*m, rs = rsqrtf(var + 1e-5f);
    #pragma unroll
    for (int i = 0; i < 8; i++){
        int d = lane + 32*i;
        sn[warp][d] = (v[i]-m)*rs*sg[d] + sb[d];
    }
    __syncthreads();
    int c = tid;
    float acc[8] = {};
    for (int k = 0; k < 256; k++){
        float w = qw[k*256 + c];
        #pragma unroll
        for (int s2 = 0; s2 < 8; s2++) acc[s2] += sn[s2][k]*w;
    }
    float bq = qb[c];
    #pragma unroll
    for (int s2 = 0; s2 < 8; s2++) g_q[(b*8+s2)*256 + c] = acc[s2] + bq;
}

// ---------------- dots + softmax over slots (warp per token) ----------------
__global__ void __launch_bounds__(256) attn_k(){
    __shared__ __align__(16) float qs[2048];
    int b = blockIdx.y, tid = threadIdx.x;
    #pragma unroll
    for (int i = 0; i < 8; i++) qs[tid + 256*i] = g_q[b*2048 + tid + 256*i];
    __syncthreads();
    int warp = tid >> 5, lane = tid & 31;
    const float4* K4 = (const float4*)(g_bufC + (size_t)b*NTOK*DIM);
    int t0 = blockIdx.x*64 + warp*8;
    for (int tt = 0; tt < 8; tt++){
        int t = t0 + tt;
        float4 k0 = K4[t*64 + lane];
        float4 k1 = K4[t*64 + 32 + lane];
        float acc[8];
        #pragma unroll
        for (int s = 0; s < 8; s++){
            const float4* q4 = (const float4*)&qs[s*256];
            float4 q0 = q4[lane], q1 = q4[lane+32];
            acc[s] = k0.x*q0.x + k0.y*q0.y + k0.z*q0.z + k0.w*q0.w
                   + k1.x*q1.x + k1.y*q1.y + k1.z*q1.z + k1.w*q1.w;
        }
        #pragma unroll
        for (int s = 0; s < 8; s++) acc[s] = wred(acc[s]) * 0.0625f;
        float mx = acc[0];
        #pragma unroll
        for (int s = 1; s < 8; s++) mx = fmaxf(mx, acc[s]);
        float e[8], sum = 0.f;
        #pragma unroll
        for (int s = 0; s < 8; s++){ e[s] = expf(acc[s] - mx); sum += e[s]; }
        float inv = 1.f/sum;
        if (lane < 8)
            g_attn[((size_t)b*NTOK + t)*8 + lane] = e[lane]*inv + 1e-8f;
    }
}

// ---------------- upd partials = attn @ V  (chunked, deterministic) + attn rowsums ----------------
__global__ void __launch_bounds__(128) updpart_k(){
    int b = blockIdx.z, dt = blockIdx.y, c = blockIdx.x;
    int tid = threadIdx.x;
    int d = dt*128 + tid;
    __shared__ float as[8][132];
    float acc[8] = {};
    float ps = 0.f;
    const float* V = g_bufA + (size_t)b*NTOK*DIM;
    for (int tb = c*512; tb < c*512 + 512; tb += 128){
        for (int i = tid; i < 1024; i += 128){
            int s = i & 7, j = i >> 3;
            as[s][j] = g_attn[((size_t)b*NTOK + tb + j)*8 + s];
        }
        __syncthreads();
        if (dt == 0 && tid < 8){
            #pragma unroll 4
            for (int j = 0; j < 128; j++) ps += as[tid][j];
        }
        #pragma unroll 4
        for (int j = 0; j < 128; j++){
            float vv = V[(size_t)(tb+j)*256 + d];
            #pragma unroll
            for (int s = 0; s < 8; s++) acc[s] += as[s][j]*vv;
        }
        __syncthreads();
    }
    #pragma unroll
    for (int s = 0; s < 8; s++)
        g_updp[(((b*8)+c)*8 + s)*256 + d] = acc[s];
    if (dt == 0 && tid < 8)
        g_psum[(b*8 + tid)*8 + c] = ps;
}

// ---------------- GRU + pre-LN + residual MLP (one block per batch) ----------------
__global__ void __launch_bounds__(256) gru_k(const float* __restrict__ wih, const float* __restrict__ whh,
                                             const float* __restrict__ bih, const float* __restrict__ bhh,
                                             const float* __restrict__ pg,  const float* __restrict__ pb,
                                             const float* __restrict__ w1,  const float* __restrict__ b1,
                                             const float* __restrict__ w2,  const float* __restrict__ b2){
    __shared__ float su[8][256];
    __shared__ float sp[8][256];
    __shared__ float sf[8][256];
    __shared__ float r_s[8];
    int b = blockIdx.x, tid = threadIdx.x, warp = tid >> 5, lane = tid & 31;
    if (tid < 8){
        float s = 0.f;
        #pragma unroll
        for (int c = 0; c < 8; c++) s += g_psum[(b*8 + tid)*8 + c];
        r_s[tid] = 1.f/s;
    }
    __syncthreads();
    #pragma unroll
    for (int i = 0; i < 8; i++){
        float s = 0.f;
        #pragma unroll
        for (int c = 0; c < 8; c++) s += g_updp[(((b*8)+c)*8 + i)*256 + tid];
        su[i][tid] = s * r_s[i];
        sp[i][tid] = g_slots[b*2048 + i*256 + tid];
    }
    __syncthreads();
    int c = tid;
    float gir[8] = {}, giz[8] = {}, gin[8] = {};
    float ghr[8] = {}, ghz[8] = {}, ghn[8] = {};
    for (int k = 0; k < 256; k++){
        float wi0 = wih[k*768 + c], wi1 = wih[k*768 + 256 + c], wi2 = wih[k*768 + 512 + c];
        float wh0 = whh[k*768 + c], wh1 = whh[k*768 + 256 + c], wh2 = whh[k*768 + 512 + c];
        #pragma unroll
        for (int s = 0; s < 8; s++){
            float us = su[s][k], psv = sp[s][k];
            gir[s] += us*wi0; giz[s] += us*wi1; gin[s] += us*wi2;
            ghr[s] += psv*wh0; ghz[s] += psv*wh1; ghn[s] += psv*wh2;
        }
    }
    float br = bih[c], bz = bih[256+c], bn_ = bih[512+c];
    float cr = bhh[c], cz = bhh[256+c], cn  = bhh[512+c];
    #pragma unroll
    for (int s = 0; s < 8; s++){
        float r = 1.f/(1.f + expf(-(gir[s]+br + ghr[s]+cr)));
        float z = 1.f/(1.f + expf(-(giz[s]+bz + ghz[s]+cz)));
        float n = tanhf(gin[s]+bn_ + r*(ghn[s]+cn));
        sf[s][c] = (1.f - z)*n + z*sp[s][c];
    }
    __syncthreads();
    {
        float v[8], s_ = 0.f, sq = 0.f;
        #pragma unroll
        for (int i = 0; i < 8; i++){ v[i] = sf[warp][lane+32*i]; s_ += v[i]; sq += v[i]*v[i]; }
        s_ = wred(s_); sq = wred(sq);
        float m = s_*(1.f/256.f), var = sq*(1.f/256.f) - m*m, rs = rsqrtf(var + 1e-5f);
        #pragma unroll
        for (int i = 0; i < 8; i++){
            int d = lane + 32*i;
            su[warp][d] = (v[i]-m)*rs*pg[d] + pb[d];
        }
    }
    __syncthreads();
    {
        float acc[8] = {};
        for (int k = 0; k < 256; k++){
            float w = w1[k*256 + c];
            #pragma unroll
            for (int s = 0; s < 8; s++) acc[s] += su[s][k]*w;
        }
        float bb = b1[c];
        #pragma unroll
        for (int s = 0; s < 8; s++) sp[s][c] = fmaxf(acc[s] + bb, 0.f);
    }
    __syncthreads();
    {
        float acc[8] = {};
        for (int k = 0; k < 256; k++){
            float w = w2[k*256 + c];
            #pragma unroll
            for (int s = 0; s < 8; s++) acc[s] += sp[s][k]*w;
        }
        float bb = b2[c];
        #pragma unroll
        for (int s = 0; s < 8; s++)
            g_slots[b*2048 + s*256 + c] = sf[s][c] + fmaxf(acc[s] + bb, 0.f);
    }
}

__global__ void copy_out_k(float* __restrict__ out){
    int idx = blockIdx.x*256 + threadIdx.x;
    out[idx] = g_slots[idx];
}

// ---------------- launch ----------------
extern "C" void kernel_launch(void* const* d_in, const int* in_sizes, int n_in,
                              void* d_out, int out_size){
    const float* x       = (const float*)d_in[0];
    const float* eps_n   = (const float*)d_in[1];
    const float* pos_w   = (const float*)d_in[2];
    const float* pos_b   = (const float*)d_in[3];
    const float* enc_g   = (const float*)d_in[4];
    const float* enc_b   = (const float*)d_in[5];
    const float* fm_w1   = (const float*)d_in[6];
    const float* fm_b1   = (const float*)d_in[7];
    const float* fm_w2   = (const float*)d_in[8];
    const float* fm_b2   = (const float*)d_in[9];
    const float* in_g    = (const float*)d_in[10];
    const float* in_b    = (const float*)d_in[11];
    const float* q_w     = (const float*)d_in[12];
    const float* q_b     = (const float*)d_in[13];
    const float* k_w     = (const float*)d_in[14];
    const float* k_b     = (const float*)d_in[15];
    const float* v_w     = (const float*)d_in[16];
    const float* v_b     = (const float*)d_in[17];
    const float* gru_wih = (const float*)d_in[18];
    const float* gru_whh = (const float*)d_in[19];
    const float* gru_bih = (const float*)d_in[20];
    const float* gru_bhh = (const float*)d_in[21];
    const float* pre_g   = (const float*)d_in[22];
    const float* pre_b   = (const float*)d_in[23];
    const float* st_w1   = (const float*)d_in[24];
    const float* st_b1   = (const float*)d_in[25];
    const float* st_w2   = (const float*)d_in[26];
    const float* st_b2   = (const float*)d_in[27];
    const float* slot_g  = (const float*)d_in[28];
    const float* slot_b  = (const float*)d_in[29];
    const float* sl_loc  = (const float*)d_in[30];
    const float* sl_lsc  = (const float*)d_in[31];

    float *bufA, *bufC;
    __half *whi, *wlo, *a16, *b16;
    cudaGetSymbolAddress((void**)&bufA, g_bufA);
    cudaGetSymbolAddress((void**)&bufC, g_bufC);
    cudaGetSymbolAddress((void**)&whi, g_whi);
    cudaGetSymbolAddress((void**)&wlo, g_wlo);
    cudaGetSymbolAddress((void**)&a16, g_a16);
    cudaGetSymbolAddress((void**)&b16, g_b16);

    const int GSMEM = 74752;   // 72KB + align slack
    cudaFuncSetAttribute(mma_gemm_k, cudaFuncAttributeMaxDynamicSharedMemorySize, GSMEM);

    prep_w_k<<<256, 256>>>(fm_w1, whi + 0*65536, wlo + 0*65536);
    prep_w_k<<<256, 256>>>(fm_w2, whi + 1*65536, wlo + 1*65536);
    prep_w_k<<<256, 256>>>(k_w,   whi + 2*65536, wlo + 2*65536);
    prep_w_k<<<256, 256>>>(v_w,   whi + 3*65536, wlo + 3*65536);

    pos_k<<<4096, 256>>>(pos_w, pos_b);
    stats_partial_k<<<dim3(256, BATCH), 256>>>(x);
    stats_final_k<<<BATCH, 256>>>();
    norm_tok_k<<<dim3(128, 8, BATCH), dim3(32, 8)>>>(x, enc_g, enc_b);

    // fm1: tokens(fp16) -> relu -> fp16
    mma_gemm_k<<<MTOT/64, 256, GSMEM>>>(a16, whi + 0*65536, wlo + 0*65536,
                                        fm_b1, (float*)0, b16, 2);
    // fm2: -> relu fp32
    mma_gemm_k<<<MTOT/64, 256, GSMEM>>>(b16, whi + 1*65536, wlo + 1*65536,
                                        fm_b2, bufA, (__half*)0, 1);
    token_ln_k<<<MTOT/8, 256>>>(bufA, in_g, in_b);
    // K
    mma_gemm_k<<<MTOT/64, 256, GSMEM>>>(a16, whi + 2*65536, wlo + 2*65536,
                                        k_b, bufC, (__half*)0, 0);
    // V
    mma_gemm_k<<<MTOT/64, 256, GSMEM>>>(a16, whi + 3*65536, wlo + 3*65536,
                                        v_b, bufA, (__half*)0, 0);

    slots_init_k<<<256, 256>>>(eps_n, sl_loc, sl_lsc);

    for (int it = 0; it < 3; it++){
        slotln_q_k<<<BATCH, 256>>>(slot_g, slot_b, q_w, q_b);
        attn_k<<<dim3(64, BATCH), 256>>>();
        updpart_k<<<dim3(8, 2, BATCH), 128>>>();
        gru_k<<<BATCH, 256>>>(gru_wih, gru_whh, gru_bih, gru_bhh,
                              pre_g, pre_b, st_w1, st_b1, st_w2, st_b2);
    }

    copy_out_k<<<256, 256>>>((float*)d_out);
}

// round 9
// speedup vs baseline: 1.2278x; 1.0982x over previous
#include <cuda_runtime.h>
#include <cuda_fp16.h>
#include <math.h>
#include <stdint.h>

#define BATCH 32
#define DIM 256
#define NTOK 4096
#define NSLOT 8
#define MTOT (BATCH*NTOK)

// ---------------- scratch (device globals; no runtime allocation) ----------------
__device__ float g_bufA[BATCH*NTOK*DIM];   // V
__device__ float g_bufC[BATCH*NTOK*DIM];   // K
__device__ __half g_a16[MTOT*DIM];         // tokens -> (after token_ln) LN'd tokens
__device__ __half g_b16[MTOT*DIM];         // fm1 out
__device__ float g_part[BATCH*256*2];
__device__ float g_stats[BATCH*2];
__device__ float g_attn[BATCH*NTOK*NSLOT]; // [b][t][s]
__device__ float g_psum[BATCH*NSLOT*8];    // [b][s][chunk]
__device__ float g_q[BATCH*NSLOT*DIM];
__device__ float g_updp[BATCH*8*NSLOT*DIM]; // [b][chunk][s][d]
__device__ float g_slots[BATCH*NSLOT*DIM];
__device__ __half g_w16[4*DIM*DIM];        // weights [N][K] fp16

__device__ __forceinline__ float wred(float v){
    #pragma unroll
    for (int o = 16; o; o >>= 1) v += __shfl_xor_sync(0xffffffffu, v, o);
    return v;
}
__device__ __forceinline__ uint32_t smem_u32(const void* p){
    uint32_t a;
    asm("{ .reg .u64 t; cvta.to.shared.u64 t, %1; cvt.u32.u64 %0, t; }" : "=r"(a) : "l"(p));
    return a;
}
__device__ __forceinline__ void ldsm4(uint32_t* r, uint32_t addr){
    asm volatile("ldmatrix.sync.aligned.m8n8.x4.shared.b16 {%0,%1,%2,%3}, [%4];"
        : "=r"(r[0]), "=r"(r[1]), "=r"(r[2]), "=r"(r[3]) : "r"(addr));
}
__device__ __forceinline__ void mma16816(float* c, const uint32_t* a, const uint32_t* b){
    asm volatile("mma.sync.aligned.m16n8k16.row.col.f32.f16.f16.f32 "
        "{%0,%1,%2,%3}, {%4,%5,%6,%7}, {%8,%9}, {%0,%1,%2,%3};"
        : "+f"(c[0]), "+f"(c[1]), "+f"(c[2]), "+f"(c[3])
        : "r"(a[0]), "r"(a[1]), "r"(a[2]), "r"(a[3]), "r"(b[0]), "r"(b[1]));
}
__device__ __forceinline__ uint32_t sw64(uint32_t boff){
    return boff ^ ((boff >> 3) & 0x30);
}
__device__ __forceinline__ void cpa16(uint32_t s, const void* g){
    asm volatile("cp.async.cg.shared.global [%0], [%1], 16;" :: "r"(s), "l"(g));
}
__device__ __forceinline__ void cpa_commit(){
    asm volatile("cp.async.commit_group;");
}
__device__ __forceinline__ float pos_val(int t, float w0, float w1, float w2, float w3, float b0){
    float gx = (float)(t >> 6) * (1.0f/63.0f);
    float gy = (float)(t & 63) * (1.0f/63.0f);
    return gx*w0 + gy*w1 + (1.f-gx)*w2 + (1.f-gy)*w3 + b0;
}

// ---------------- weight prep (all 4 sets): transpose [K,N]->[N,K], fp16 ----------------
__global__ void prep_w_k(const float* __restrict__ w0, const float* __restrict__ w1,
                         const float* __restrict__ w2, const float* __restrict__ w3,
                         __half* __restrict__ wh){
    int set = blockIdx.y;
    const float* w = (set == 0) ? w0 : (set == 1) ? w1 : (set == 2) ? w2 : w3;
    int idx = blockIdx.x*256 + threadIdx.x;
    int n = idx >> 8, k = idx & 255;
    wh[set*65536 + idx] = __float2half_rn(w[k*256 + n]);
}

// ---------------- whole-image LN stats (inline positional embed) ----------------
__global__ void __launch_bounds__(256) stats_partial_k(const float* __restrict__ x,
                                                       const float* __restrict__ pw,
                                                       const float* __restrict__ pb){
    int b = blockIdx.y, p = blockIdx.x, tid = threadIdx.x;
    const float* xb = x + (size_t)b*(DIM*NTOK) + (size_t)p*NTOK;
    float w0 = pw[p], w1 = pw[256+p], w2 = pw[512+p], w3 = pw[768+p], b0 = pb[p];
    float s = 0.f, sq = 0.f;
    #pragma unroll
    for (int j = 0; j < 16; j++){
        int t = tid + j*256;
        float v = xb[t] + pos_val(t, w0, w1, w2, w3, b0);
        s += v; sq += v*v;
    }
    __shared__ float ss[256], sqs[256];
    ss[tid] = s; sqs[tid] = sq; __syncthreads();
    for (int st = 128; st; st >>= 1){
        if (tid < st){ ss[tid] += ss[tid+st]; sqs[tid] += sqs[tid+st]; }
        __syncthreads();
    }
    if (!tid){ g_part[(b*256+p)*2] = ss[0]; g_part[(b*256+p)*2+1] = sqs[0]; }
}

__global__ void stats_final_k(){
    int b = blockIdx.x, tid = threadIdx.x;
    __shared__ float ss[256], sqs[256];
    ss[tid]  = g_part[(b*256+tid)*2];
    sqs[tid] = g_part[(b*256+tid)*2+1];
    __syncthreads();
    for (int st = 128; st; st >>= 1){
        if (tid < st){ ss[tid] += ss[tid+st]; sqs[tid] += sqs[tid+st]; }
        __syncthreads();
    }
    if (!tid){
        const float invN = 1.0f/1048576.0f;
        float m = ss[0]*invN;
        float var = sqs[0]*invN - m*m;
        g_stats[b*2] = m;
        g_stats[b*2+1] = rsqrtf(var + 1e-5f);
    }
}

// ---------------- normalize + transpose -> fp16 token plane (inline pos) ----------------
__global__ void __launch_bounds__(256) norm_tok_k(const float* __restrict__ x,
                                                  const float* __restrict__ pw,
                                                  const float* __restrict__ pb,
                                                  const float* __restrict__ eg,
                                                  const float* __restrict__ eb){
    __shared__ float sh[32][33];
    int b = blockIdx.z;
    int d0 = blockIdx.y*32, t0 = blockIdx.x*32;
    int tx = threadIdx.x, ty = threadIdx.y;
    float mean = g_stats[b*2], rstd = g_stats[b*2+1];
    const float* xb = x + (size_t)b*(DIM*NTOK);
    #pragma unroll
    for (int r = 0; r < 4; r++)
        sh[ty+8*r][tx] = xb[(size_t)(d0+ty+8*r)*NTOK + t0 + tx];
    __syncthreads();
    int dcol = d0 + tx;
    float w0 = pw[dcol], w1 = pw[256+dcol], w2 = pw[512+dcol], w3 = pw[768+dcol], b0 = pb[dcol];
    size_t ob = (size_t)b*(NTOK*DIM);
    #pragma unroll
    for (int r = 0; r < 4; r++){
        int trow = t0 + ty + 8*r;
        int pi = trow*DIM + dcol;
        float v = sh[tx][ty+8*r] + pos_val(trow, w0, w1, w2, w3, b0);
        float o = (v - mean)*rstd*eg[pi] + eb[pi];
        g_a16[ob + pi] = __float2half_rn(o);
    }
}

// ---------------- HMMA GEMM: C[M,256] = act(A16 @ W16 + bias) ----------------
// Single fp16 plane each side. CTA M=64 x N=256, 8 warps (2m x 4n), warp 32x64.
// K-chunk 32, double-buffered cp.async. smem 40KB, 2 CTAs/SM.
// mode: 0 = fp32 out, 1 = fp32 relu out, 2 = relu + fp16 out
__global__ void __launch_bounds__(256, 2) mma_gemm_k(
        const __half* __restrict__ A16, const __half* __restrict__ W16,
        const float* __restrict__ bias,
        float* __restrict__ C, __half* __restrict__ C16, int mode){
    extern __shared__ char dsm[];
    __shared__ float s_bias[256];
    int tid = threadIdx.x;
    uint32_t raw = smem_u32(dsm);
    uint32_t sb = (raw + 1023) & ~1023u;
    uint32_t aA = sb, aB = sb + 8192;   // A: 2 x 4KB, B: 2 x 16KB

    s_bias[tid] = bias[tid];

    size_t bm = (size_t)blockIdx.x * 64;
    int lane = tid & 31, wid = tid >> 5;
    int wm = wid & 1, wn = wid >> 1;    // 2(m) x 4(n)

    float acc[2][8][4] = {};

    auto prefetch = [&](int c, int buf){
        int k0 = c * 32;
        {
            int r = tid >> 2, qc = tid & 3;
            uint32_t soff = (uint32_t)(buf*4096) + sw64((uint32_t)(r*64 + qc*16));
            cpa16(aA + soff, A16 + (bm + r)*256 + k0 + qc*8);
        }
        #pragma unroll
        for (int p = 0; p < 4; p++){
            int id = tid + p*256;
            int r = id >> 2, qc = id & 3;
            uint32_t soff = (uint32_t)(buf*16384) + sw64((uint32_t)(r*64 + qc*16));
            cpa16(aB + soff, W16 + (size_t)r*256 + k0 + qc*8);
        }
    };

    prefetch(0, 0);
    cpa_commit();

    #pragma unroll 1
    for (int c = 0; c < 8; c++){
        int buf = c & 1;
        if (c < 7){
            prefetch(c+1, buf ^ 1);
            cpa_commit();
            asm volatile("cp.async.wait_group 1;");
        } else {
            asm volatile("cp.async.wait_group 0;");
        }
        __syncthreads();

        #pragma unroll
        for (int ks = 0; ks < 2; ks++){
            uint32_t Ah[2][4];
            #pragma unroll
            for (int i = 0; i < 2; i++){
                uint32_t row = wm*32 + i*16 + (lane & 15);
                uint32_t sw = sw64(row*64 + ks*32 + (lane >> 4)*16);
                ldsm4(Ah[i], aA + buf*4096 + sw);
            }
            #pragma unroll
            for (int j2 = 0; j2 < 4; j2++){
                uint32_t row = wn*64 + j2*16 + (lane >> 4)*8 + (lane & 7);
                uint32_t sw = sw64(row*64 + ks*32 + ((lane >> 3) & 1)*16);
                uint32_t bh[4];
                ldsm4(bh, aB + buf*16384 + sw);
                #pragma unroll
                for (int i = 0; i < 2; i++){
                    mma16816(acc[i][2*j2],   Ah[i], bh);
                    mma16816(acc[i][2*j2+1], Ah[i], bh+2);
                }
            }
        }
        __syncthreads();
    }

    int row0 = (int)bm + wm*32 + (lane >> 2);
    int col0 = wn*64 + 2*(lane & 3);
    #pragma unroll
    for (int i = 0; i < 2; i++){
        #pragma unroll
        for (int j = 0; j < 8; j++){
            int col = col0 + j*8;
            float b0 = s_bias[col], b1 = s_bias[col+1];
            float v00 = acc[i][j][0] + b0, v01 = acc[i][j][1] + b1;
            float v10 = acc[i][j][2] + b0, v11 = acc[i][j][3] + b1;
            if (mode >= 1){
                v00 = fmaxf(v00, 0.f); v01 = fmaxf(v01, 0.f);
                v10 = fmaxf(v10, 0.f); v11 = fmaxf(v11, 0.f);
            }
            size_t r0 = (size_t)(row0 + i*16)*256 + col;
            size_t r1 = r0 + 8*256;
            if (mode == 2){
                *(__half2*)&C16[r0] = __halves2half2(__float2half_rn(v00), __float2half_rn(v01));
                *(__half2*)&C16[r1] = __halves2half2(__float2half_rn(v10), __float2half_rn(v11));
            } else {
                float2 o0 = {v00, v01}, o1 = {v10, v11};
                *(float2*)&C[r0] = o0;
                *(float2*)&C[r1] = o1;
            }
        }
    }
}

// ---------------- per-token LayerNorm, fp16 in-place on g_a16 ----------------
__global__ void __launch_bounds__(256) token_ln_k(const float* __restrict__ g,
                                                  const float* __restrict__ be){
    int warp = threadIdx.x >> 5, lane = threadIdx.x & 31;
    size_t row = (size_t)blockIdx.x*8 + warp;
    __half2* H2 = (__half2*)(g_a16 + row*DIM);   // 128 half2
    float2 v[4];
    float s = 0.f, sq = 0.f;
    #pragma unroll
    for (int q = 0; q < 4; q++){
        v[q] = __half22float2(H2[lane + 32*q]);
        s += v[q].x + v[q].y;
        sq += v[q].x*v[q].x + v[q].y*v[q].y;
    }
    s = wred(s); sq = wred(sq);
    float m = s*(1.0f/256.0f);
    float var = sq*(1.0f/256.0f) - m*m;
    float rs = rsqrtf(var + 1e-5f);
    const float2* g2 = (const float2*)g;
    const float2* b2 = (const float2*)be;
    #pragma unroll
    for (int q = 0; q < 4; q++){
        int d2 = lane + 32*q;
        float2 gg = g2[d2], bb = b2[d2];
        float ox = (v[q].x - m)*rs*gg.x + bb.x;
        float oy = (v[q].y - m)*rs*gg.y + bb.y;
        H2[d2] = __halves2half2(__float2half_rn(ox), __float2half_rn(oy));
    }
}

// ---------------- slots init ----------------
__global__ void slots_init_k(const float* __restrict__ eps, const float* __restrict__ loc,
                             const float* __restrict__ lsc){
    int idx = blockIdx.x*256 + threadIdx.x;
    int d = idx & 255;
    g_slots[idx] = loc[d] + expf(lsc[d]) * eps[idx];
}

// ---------------- slot LN + Q projection ----------------
__global__ void __launch_bounds__(256) slotln_q_k(const float* __restrict__ sg,
                                                  const float* __restrict__ sb,
                                                  const float* __restrict__ qw,
                                                  const float* __restrict__ qb){
    __shared__ float sn[8][256];
    int b = blockIdx.x, tid = threadIdx.x, warp = tid >> 5, lane = tid & 31;
    const float* sl = g_slots + (b*8 + warp)*256;
    float v[8]; float s = 0.f, sq = 0.f;
    #pragma unroll
    for (int i = 0; i < 8; i++){ v[i] = sl[lane + 32*i]; s += v[i]; sq += v[i]*v[i]; }
    s = wred(s); sq = wred(sq);
    float m = s*(1.f/256.f), var = sq*(1.f/256.f) - m*m, rs = rsqrtf(var + 1e-5f);
    #pragma unroll
    for (int i = 0; i < 8; i++){
        int d = lane + 32*i;
        sn[warp][d] = (v[i]-m)*rs*sg[d] + sb[d];
    }
    __syncthreads();
    int c = tid;
    float acc[8] = {};
    for (int k = 0; k < 256; k++){
        float w = qw[k*256 + c];
        #pragma unroll
        for (int s2 = 0; s2 < 8; s2++) acc[s2] += sn[s2][k]*w;
    }
    float bq = qb[c];
    #pragma unroll
    for (int s2 = 0; s2 < 8; s2++) g_q[(b*8+s2)*256 + c] = acc[s2] + bq;
}

// ---------------- dots + softmax over slots (warp per token) ----------------
__global__ void __launch_bounds__(256) attn_k(){
    __shared__ __align__(16) float qs[2048];
    int b = blockIdx.y, tid = threadIdx.x;
    #pragma unroll
    for (int i = 0; i < 8; i++) qs[tid + 256*i] = g_q[b*2048 + tid + 256*i];
    __syncthreads();
    int warp = tid >> 5, lane = tid & 31;
    const float4* K4 = (const float4*)(g_bufC + (size_t)b*NTOK*DIM);
    int t0 = blockIdx.x*64 + warp*8;
    for (int tt = 0; tt < 8; tt++){
        int t = t0 + tt;
        float4 k0 = K4[t*64 + lane];
        float4 k1 = K4[t*64 + 32 + lane];
        float acc[8];
        #pragma unroll
        for (int s = 0; s < 8; s++){
            const float4* q4 = (const float4*)&qs[s*256];
            float4 q0 = q4[lane], q1 = q4[lane+32];
            acc[s] = k0.x*q0.x + k0.y*q0.y + k0.z*q0.z + k0.w*q0.w
                   + k1.x*q1.x + k1.y*q1.y + k1.z*q1.z + k1.w*q1.w;
        }
        #pragma unroll
        for (int s = 0; s < 8; s++) acc[s] = wred(acc[s]) * 0.0625f;
        float mx = acc[0];
        #pragma unroll
        for (int s = 1; s < 8; s++) mx = fmaxf(mx, acc[s]);
        float e[8], sum = 0.f;
        #pragma unroll
        for (int s = 0; s < 8; s++){ e[s] = expf(acc[s] - mx); sum += e[s]; }
        float inv = 1.f/sum;
        if (lane < 8)
            g_attn[((size_t)b*NTOK + t)*8 + lane] = e[lane]*inv + 1e-8f;
    }
}

// ---------------- upd partials = attn @ V (chunked, deterministic) + rowsums ----------------
__global__ void __launch_bounds__(128) updpart_k(){
    int b = blockIdx.z, dt = blockIdx.y, c = blockIdx.x;
    int tid = threadIdx.x;
    int d = dt*128 + tid;
    __shared__ float as[8][132];
    float acc[8] = {};
    float ps = 0.f;
    const float* V = g_bufA + (size_t)b*NTOK*DIM;
    for (int tb = c*512; tb < c*512 + 512; tb += 128){
        for (int i = tid; i < 1024; i += 128){
            int s = i & 7, j = i >> 3;
            as[s][j] = g_attn[((size_t)b*NTOK + tb + j)*8 + s];
        }
        __syncthreads();
        if (dt == 0 && tid < 8){
            #pragma unroll 4
            for (int j = 0; j < 128; j++) ps += as[tid][j];
        }
        #pragma unroll 4
        for (int j = 0; j < 128; j++){
            float vv = V[(size_t)(tb+j)*256 + d];
            #pragma unroll
            for (int s = 0; s < 8; s++) acc[s] += as[s][j]*vv;
        }
        __syncthreads();
    }
    #pragma unroll
    for (int s = 0; s < 8; s++)
        g_updp[(((b*8)+c)*8 + s)*256 + d] = acc[s];
    if (dt == 0 && tid < 8)
        g_psum[(b*8 + tid)*8 + c] = ps;
}

// ---------------- GRU + pre-LN + residual MLP (one block per batch) ----------------
__global__ void __launch_bounds__(256) gru_k(const float* __restrict__ wih, const float* __restrict__ whh,
                                             const float* __restrict__ bih, const float* __restrict__ bhh,
                                             const float* __restrict__ pg,  const float* __restrict__ pb,
                                             const float* __restrict__ w1,  const float* __restrict__ b1,
                                             const float* __restrict__ w2,  const float* __restrict__ b2){
    __shared__ float su[8][256];
    __shared__ float sp[8][256];
    __shared__ float sf[8][256];
    __shared__ float r_s[8];
    int b = blockIdx.x, tid = threadIdx.x, warp = tid >> 5, lane = tid & 31;
    if (tid < 8){
        float s = 0.f;
        #pragma unroll
        for (int c = 0; c < 8; c++) s += g_psum[(b*8 + tid)*8 + c];
        r_s[tid] = 1.f/s;
    }
    __syncthreads();
    #pragma unroll
    for (int i = 0; i < 8; i++){
        float s = 0.f;
        #pragma unroll
        for (int c = 0; c < 8; c++) s += g_updp[(((b*8)+c)*8 + i)*256 + tid];
        su[i][tid] = s * r_s[i];
        sp[i][tid] = g_slots[b*2048 + i*256 + tid];
    }
    __syncthreads();
    int c = tid;
    float gir[8] = {}, giz[8] = {}, gin[8] = {};
    float ghr[8] = {}, ghz[8] = {}, ghn[8] = {};
    for (int k = 0; k < 256; k++){
        float wi0 = wih[k*768 + c], wi1 = wih[k*768 + 256 + c], wi2 = wih[k*768 + 512 + c];
        float wh0 = whh[k*768 + c], wh1 = whh[k*768 + 256 + c], wh2 = whh[k*768 + 512 + c];
        #pragma unroll
        for (int s = 0; s < 8; s++){
            float us = su[s][k], psv = sp[s][k];
            gir[s] += us*wi0; giz[s] += us*wi1; gin[s] += us*wi2;
            ghr[s] += psv*wh0; ghz[s] += psv*wh1; ghn[s] += psv*wh2;
        }
    }
    float br = bih[c], bz = bih[256+c], bn_ = bih[512+c];
    float cr = bhh[c], cz = bhh[256+c], cn  = bhh[512+c];
    #pragma unroll
    for (int s = 0; s < 8; s++){
        float r = 1.f/(1.f + expf(-(gir[s]+br + ghr[s]+cr)));
        float z = 1.f/(1.f + expf(-(giz[s]+bz + ghz[s]+cz)));
        float n = tanhf(gin[s]+bn_ + r*(ghn[s]+cn));
        sf[s][c] = (1.f - z)*n + z*sp[s][c];
    }
    __syncthreads();
    {
        float v[8], s_ = 0.f, sq = 0.f;
        #pragma unroll
        for (int i = 0; i < 8; i++){ v[i] = sf[warp][lane+32*i]; s_ += v[i]; sq += v[i]*v[i]; }
        s_ = wred(s_); sq = wred(sq);
        float m = s_*(1.f/256.f), var = sq*(1.f/256.f) - m*m, rs = rsqrtf(var + 1e-5f);
        #pragma unroll
        for (int i = 0; i < 8; i++){
            int d = lane + 32*i;
            su[warp][d] = (v[i]-m)*rs*pg[d] + pb[d];
        }
    }
    __syncthreads();
    {
        float acc[8] = {};
        for (int k = 0; k < 256; k++){
            float w = w1[k*256 + c];
            #pragma unroll
            for (int s = 0; s < 8; s++) acc[s] += su[s][k]*w;
        }
        float bb = b1[c];
        #pragma unroll
        for (int s = 0; s < 8; s++) sp[s][c] = fmaxf(acc[s] + bb, 0.f);
    }
    __syncthreads();
    {
        float acc[8] = {};
        for (int k = 0; k < 256; k++){
            float w = w2[k*256 + c];
            #pragma unroll
            for (int s = 0; s < 8; s++) acc[s] += sp[s][k]*w;
        }
        float bb = b2[c];
        #pragma unroll
        for (int s = 0; s < 8; s++)
            g_slots[b*2048 + s*256 + c] = sf[s][c] + fmaxf(acc[s] + bb, 0.f);
    }
}

__global__ void copy_out_k(float* __restrict__ out){
    int idx = blockIdx.x*256 + threadIdx.x;
    out[idx] = g_slots[idx];
}

// ---------------- launch ----------------
extern "C" void kernel_launch(void* const* d_in, const int* in_sizes, int n_in,
                              void* d_out, int out_size){
    const float* x       = (const float*)d_in[0];
    const float* eps_n   = (const float*)d_in[1];
    const float* pos_w   = (const float*)d_in[2];
    const float* pos_b   = (const float*)d_in[3];
    const float* enc_g   = (const float*)d_in[4];
    const float* enc_b   = (const float*)d_in[5];
    const float* fm_w1   = (const float*)d_in[6];
    const float* fm_b1   = (const float*)d_in[7];
    const float* fm_w2   = (const float*)d_in[8];
    const float* fm_b2   = (const float*)d_in[9];
    const float* in_g    = (const float*)d_in[10];
    const float* in_b    = (const float*)d_in[11];
    const float* q_w     = (const float*)d_in[12];
    const float* q_b     = (const float*)d_in[13];
    const float* k_w     = (const float*)d_in[14];
    const float* k_b     = (const float*)d_in[15];
    const float* v_w     = (const float*)d_in[16];
    const float* v_b     = (const float*)d_in[17];
    const float* gru_wih = (const float*)d_in[18];
    const float* gru_whh = (const float*)d_in[19];
    const float* gru_bih = (const float*)d_in[20];
    const float* gru_bhh = (const float*)d_in[21];
    const float* pre_g   = (const float*)d_in[22];
    const float* pre_b   = (const float*)d_in[23];
    const float* st_w1   = (const float*)d_in[24];
    const float* st_b1   = (const float*)d_in[25];
    const float* st_w2   = (const float*)d_in[26];
    const float* st_b2   = (const float*)d_in[27];
    const float* slot_g  = (const float*)d_in[28];
    const float* slot_b  = (const float*)d_in[29];
    const float* sl_loc  = (const float*)d_in[30];
    const float* sl_lsc  = (const float*)d_in[31];

    float *bufA, *bufC;
    __half *w16, *a16, *b16;
    cudaGetSymbolAddress((void**)&bufA, g_bufA);
    cudaGetSymbolAddress((void**)&bufC, g_bufC);
    cudaGetSymbolAddress((void**)&w16, g_w16);
    cudaGetSymbolAddress((void**)&a16, g_a16);
    cudaGetSymbolAddress((void**)&b16, g_b16);

    const int GSMEM = 41984;   // 40KB + align slack
    cudaFuncSetAttribute(mma_gemm_k, cudaFuncAttributeMaxDynamicSharedMemorySize, GSMEM);

    prep_w_k<<<dim3(256, 4), 256>>>(fm_w1, fm_w2, k_w, v_w, w16);          // idx 0
    stats_partial_k<<<dim3(256, BATCH), 256>>>(x, pos_w, pos_b);           // idx 1
    stats_final_k<<<BATCH, 256>>>();                                       // idx 2
    norm_tok_k<<<dim3(128, 8, BATCH), dim3(32, 8)>>>(x, pos_w, pos_b,      // idx 3 (profiled)
                                                     enc_g, enc_b);

    // fm1: tokens(fp16) -> relu -> fp16
    mma_gemm_k<<<MTOT/64, 256, GSMEM>>>(a16, w16 + 0*65536, fm_b1, (float*)0, b16, 2);
    // fm2: -> relu -> fp16 (into a16; tokens consumed)
    mma_gemm_k<<<MTOT/64, 256, GSMEM>>>(b16, w16 + 1*65536, fm_b2, (float*)0, a16, 2);
    token_ln_k<<<MTOT/8, 256>>>(in_g, in_b);   // in-place on a16
    // K
    mma_gemm_k<<<MTOT/64, 256, GSMEM>>>(a16, w16 + 2*65536, k_b, bufC, (__half*)0, 0);
    // V
    mma_gemm_k<<<MTOT/64, 256, GSMEM>>>(a16, w16 + 3*65536, v_b, bufA, (__half*)0, 0);

    slots_init_k<<<256, 256>>>(eps_n, sl_loc, sl_lsc);

    for (int it = 0; it < 3; it++){
        slotln_q_k<<<BATCH, 256>>>(slot_g, slot_b, q_w, q_b);
        attn_k<<<dim3(64, BATCH), 256>>>();
        updpart_k<<<dim3(8, 2, BATCH), 128>>>();
        gru_k<<<BATCH, 256>>>(gru_wih, gru_whh, gru_bih, gru_bhh,
                              pre_g, pre_b, st_w1, st_b1, st_w2, st_b2);
    }

    copy_out_k<<<256, 256>>>((float*)d_out);
}